// round 7
// baseline (speedup 1.0000x reference)
#include <cuda_runtime.h>
#include <math.h>

#define NUMR    100
#define BATCH   2048
#define NVAR    192
#define NEQC    30
#define NHDIM   222
#define MAXIT   15
#define SPB     4
#define NTHREADS 256

// shared memory float offsets (28648 floats = 114,592 B -> 2 CTAs/SM)
#define OFF_X    0        // 300*32 = 9600
#define OFF_Y    9600     // 3*100*24 = 7200
#define OFF_W    16800    // 7200
#define OFF_P    24000    // 24*36 = 864
#define OFF_RHS  24864    // union: rhs 4*196=784  |  PART 9*8*25=1800
#define OFF_PART 24864
#define OFF_DL   26664    // 24*36 = 864 (sum over t)
#define OFF_G    27528    // 32*32 = 1024
#define OFF_RED  28552    // 8*12 = 96
#define SMEM_FLOATS 28648

typedef unsigned long long ull;

__device__ __align__(16) float Qpad[NVAR * NVAR];

__device__ __forceinline__ void fma2(ull& d, ull a, ull b) {
    asm("fma.rn.f32x2 %0, %1, %2, %0;" : "+l"(d) : "l"(a), "l"(b));
}
__device__ __forceinline__ float hadd2(ull v) {
    float lo, hi;
    asm("mov.b64 {%0, %1}, %2;" : "=f"(lo), "=f"(hi) : "l"(v));
    return lo + hi;
}
__device__ __forceinline__ ull pack2(float v) {
    ull r; asm("mov.b64 %0, {%1, %1};" : "=l"(r) : "f"(v)); return r;
}
__device__ __forceinline__ void unpack2(float& lo, float& hi, ull v) {
    asm("mov.b64 {%0, %1}, %2;" : "=f"(lo), "=f"(hi) : "l"(v));
}

__global__ void qprep_kernel(const float* __restrict__ Qi)
{
    int idx = blockIdx.x * blockDim.x + threadIdx.x;
    if (idx < NVAR * NVAR) {
        int j = idx / NVAR;
        int k = idx - j * NVAR;
        Qpad[idx] = Qi[j * NHDIM + k];
    }
}

__global__ void __launch_bounds__(NTHREADS, 2)
proj_filter_kernel(const float* __restrict__ lamda,
                   const float* __restrict__ c_in_g,
                   const float* __restrict__ c_samp,
                   const float* __restrict__ b_eq,
                   const float* __restrict__ Av,
                   const float* __restrict__ Aa,
                   const float* __restrict__ Ap,
                   const float* __restrict__ Qi,
                   float* __restrict__ out)
{
    extern __shared__ float sm[];
    const int tid   = threadIdx.x;
    const int warp  = tid >> 5;       // 0..7
    const int lane  = tid & 31;
    const int samp  = warp >> 1;      // 0..3
    const int h     = warp & 1;
    const int mb    = 3 * h;
    const int s     = blockIdx.x * SPB + samp;
    const int col0  = samp * 6 + mb;  // first owned column (of 24)

    // phase-B role: 256 threads x 3 rows = 768 = 192 rows x 4 samples
    const int bs  = lane & 3;         // sample 0..3
    const int br  = lane >> 2;        // 0..7
    const int bj0 = warp * 24 + br;   // rows bj0, bj0+8, bj0+16

    const float Vb[3] = {0.8f, 1.8f, 3.14159265358979323846f};

    // ---- stage X (300 rows x 32) ----
    for (int idx = tid; idx < 300 * 32; idx += NTHREADS) {
        int t   = idx / 3200;
        int rem = idx - t * 3200;
        int r = rem >> 5;
        int c = rem & 31;
        const float* Asrc = (t == 0) ? Av : ((t == 1) ? Aa : Ap);
        sm[OFF_X + (t * NUMR + r) * 32 + c] = Asrc[r * NVAR + c];
    }
    __syncthreads();

    // ---- G = sum_t X_t^T X_t (8 warps x 4 rows) ----
    {
        int b = lane;
        float g0 = 0.f, g1 = 0.f, g2 = 0.f, g3 = 0.f;
        for (int gg = 0; gg < 300; gg++) {
            const float* xr = &sm[OFF_X + gg * 32];
            float xb = xr[b];
            g0 += xr[warp]      * xb;
            g1 += xr[warp + 8]  * xb;
            g2 += xr[warp + 16] * xb;
            g3 += xr[warp + 24] * xb;
        }
        sm[OFF_G + (warp     ) * 32 + b] = g0;
        sm[OFF_G + (warp +  8) * 32 + b] = g1;
        sm[OFF_G + (warp + 16) * 32 + b] = g2;
        sm[OFF_G + (warp + 24) * 32 + b] = g3;
    }

    // ---- per-sample state (lsum = sum_t lambda_t) ----
    float cin[3], cprev[3], lsum[3], sdl[3], pbq[3];
#pragma unroll
    for (int m = 0; m < 3; m++) {
        int j = (mb + m) * 32 + lane;
        cin[m]   = c_in_g[s * NVAR + j];
        cprev[m] = c_samp[s * NVAR + j];
        const float* lp = lamda + s * (3 * NVAR) + j;
        lsum[m] = lp[0] + lp[NVAR] + lp[2 * NVAR];
    }

#pragma unroll
    for (int jg = 0; jg < 3; jg++) {
        int j = bj0 + jg * 8;
        float a = 0.f;
        const float* bq = b_eq + (blockIdx.x * SPB + bs) * NEQC;
        for (int k = 0; k < NEQC; k++)
            a += Qi[j * NHDIM + NVAR + k] * bq[k];
        pbq[jg] = a;
    }

    // stage initial P (p0 = c_samp)
#pragma unroll
    for (int m = 0; m < 3; m++)
        sm[OFF_P + (col0 + m) * 36 + lane] = cprev[m];
    __syncthreads();   // X, G, P ready

    // ---- D0: y0, w0 (row-parallel, lane = col<24) ----
    {
        ull PA[16];
        const ulonglong2* Pc = (const ulonglong2*)&sm[OFF_P + lane * 36];
#pragma unroll
        for (int q = 0; q < 8; q++) {
            ulonglong2 a = Pc[q]; PA[2*q] = a.x; PA[2*q+1] = a.y;
        }
#pragma unroll
        for (int t = 0; t < 3; t++) {
            float V = Vb[t];
#pragma unroll
            for (int i = 0; i < 13; i++) {
                int r = warp + 8 * i;
                if (r < NUMR) {
                    const ulonglong2* Xr = (const ulonglong2*)&sm[OFF_X + (t * NUMR + r) * 32];
                    ull a0 = 0, a1 = 0;
#pragma unroll
                    for (int q = 0; q < 8; q++) {
                        ulonglong2 x = Xr[q];
                        fma2(a0, x.x, PA[2*q]);
                        fma2(a1, x.y, PA[2*q+1]);
                    }
                    float yn = hadd2(a0) + hadd2(a1);
                    if (lane < 24) {
                        int base = t * 2400 + r * 24 + lane;
                        sm[OFF_Y + base] = yn;
                        sm[OFF_W + base] = fmaxf(yn - V, 0.f) - fmaxf(-yn - V, 0.f);
                    }
                }
            }
        }
    }
    __syncthreads();

    // ---- E0: sdl0 = sum_t X_t^T w0_t  (warp owns 4 k) ----
    {
        int k0 = warp << 2;
        float sk0 = 0.f, sk1 = 0.f, sk2 = 0.f, sk3 = 0.f;
#pragma unroll
        for (int t = 0; t < 3; t++) {
            ull d0 = 0, d1 = 0;
            for (int r = 0; r < NUMR; r++) {
                ulonglong2 xp = *(const ulonglong2*)&sm[OFF_X + (t * NUMR + r) * 32 + k0];
                ull w = pack2(sm[OFF_W + t * 2400 + r * 24 + lane]);
                fma2(d0, xp.x, w);
                fma2(d1, xp.y, w);
            }
            float a, b, c, d;
            unpack2(a, b, d0); unpack2(c, d, d1);
            sk0 += a; sk1 += b; sk2 += c; sk3 += d;
        }
        if (lane < 24) {
            int base = OFF_DL + lane * 36 + k0;
            sm[base] = sk0; sm[base+1] = sk1; sm[base+2] = sk2; sm[base+3] = sk3;
        }
    }
    __syncthreads();

#pragma unroll
    for (int m = 0; m < 3; m++)
        sdl[m] = sm[OFF_DL + (col0 + m) * 36 + lane];

    float fp_sum = 0.f, rp_sum = 0.f;

    const int j0 = (bj0     ) * 48;   // Q row offsets in 16B units
    const int j1 = (bj0 +  8) * 48;
    const int j2 = (bj0 + 16) * 48;

    for (int it = 0; it < MAXIT; it++) {
        // ======== A: gp = G@p ; rhs = lsum + cin + 2 gp - sdl ========
        {
            const float* Gm = &sm[OFF_G];
            const float* P0 = &sm[OFF_P + col0 * 36];
            const float* P1 = P0 + 36;
            const float* P2 = P0 + 72;
            float g0 = 0.f, g1 = 0.f, g2 = 0.f;
#pragma unroll 8
            for (int k = 0; k < 32; k++) {
                float gk = Gm[k * 32 + lane];
                g0 += gk * P0[k]; g1 += gk * P1[k]; g2 += gk * P2[k];
            }
            float gpv[3] = {g0, g1, g2};
#pragma unroll
            for (int m = 0; m < 3; m++)
                sm[OFF_RHS + samp * 196 + (mb + m) * 32 + lane] =
                    lsum[m] + cin[m] + 2.f * gpv[m] - sdl[m];
        }
        __syncthreads();   // rhs ready

        // ======== B: primal = Qpad @ rhs + pb (L2-streamed, barrier-free) ========
        {
            const ulonglong2* Qp = (const ulonglong2*)Qpad;
            const ulonglong2* RV = (const ulonglong2*)&sm[OFF_RHS + bs * 196];
            ull a00 = 0, a01 = 0, a10 = 0, a11 = 0, a20 = 0, a21 = 0;
#pragma unroll 4
            for (int kk = 0; kk < 48; kk++) {
                ulonglong2 q0 = Qp[j0 + kk];
                ulonglong2 q1 = Qp[j1 + kk];
                ulonglong2 q2 = Qp[j2 + kk];
                ulonglong2 rv = RV[kk];
                fma2(a00, q0.x, rv.x); fma2(a01, q0.y, rv.y);
                fma2(a10, q1.x, rv.x); fma2(a11, q1.y, rv.y);
                fma2(a20, q2.x, rv.x); fma2(a21, q2.y, rv.y);
            }
            float p0 = hadd2(a00) + hadd2(a01) + pbq[0];
            float p1 = hadd2(a10) + hadd2(a11) + pbq[1];
            float p2 = hadd2(a20) + hadd2(a21) + pbq[2];
            int ja = bj0, jb = bj0 + 8, jc = bj0 + 16;
            sm[OFF_P + (bs * 6 + (ja >> 5)) * 36 + (ja & 31)] = p0;
            sm[OFF_P + (bs * 6 + (jb >> 5)) * 36 + (jb & 31)] = p1;
            sm[OFF_P + (bs * 6 + (jc >> 5)) * 36 + (jc & 31)] = p2;
        }
        __syncthreads();   // P_new ready

        // ======== C: dc ========
        float dc = 0.f;
#pragma unroll
        for (int m = 0; m < 3; m++) {
            float pr = sm[OFF_P + (col0 + m) * 36 + lane];
            float dd = pr - cprev[m];
            dc += dd * dd;
            cprev[m] = pr;
        }

        // ======== D: y/w update + res/ds partials (row-parallel) ========
        {
            ull PA[16];
            const ulonglong2* Pc = (const ulonglong2*)&sm[OFF_P + lane * 36];
#pragma unroll
            for (int q = 0; q < 8; q++) {
                ulonglong2 a = Pc[q]; PA[2*q] = a.x; PA[2*q+1] = a.y;
            }
#pragma unroll
            for (int t = 0; t < 3; t++) {
                float V = Vb[t];
                float ra = 0.f, da = 0.f;
#pragma unroll
                for (int i = 0; i < 13; i++) {
                    int r = warp + 8 * i;
                    if (r < NUMR) {
                        const ulonglong2* Xr = (const ulonglong2*)&sm[OFF_X + (t * NUMR + r) * 32];
                        ull a0 = 0, a1 = 0;
#pragma unroll
                        for (int q = 0; q < 8; q++) {
                            ulonglong2 x = Xr[q];
                            fma2(a0, x.x, PA[2*q]);
                            fma2(a1, x.y, PA[2*q+1]);
                        }
                        float yn = hadd2(a0) + hadd2(a1);
                        int base = t * 2400 + r * 24 + lane;
                        float yo = sm[OFF_Y + base];
                        float rt = fmaxf(yn - V, 0.f);
                        float rb = fmaxf(-yn - V, 0.f);
                        ra += rt * rt + rb * rb;
                        float d1 = fmaxf(V - yn, 0.f) - fmaxf(V - yo, 0.f);
                        float d2 = fmaxf(V + yn, 0.f) - fmaxf(V + yo, 0.f);
                        da += d1 * d1 + d2 * d2;
                        if (lane < 24) {
                            sm[OFF_Y + base] = yn;
                            sm[OFF_W + base] = rt - rb;
                        }
                    }
                }
                if (lane < 24) {
                    sm[OFF_PART + ((0 * 3 + t) * 8 + warp) * 25 + lane] = ra;
                    sm[OFF_PART + ((1 * 3 + t) * 8 + warp) * 25 + lane] = da;
                }
            }
        }
        __syncthreads();   // W, res/ds partials ready

        // ======== E: dl = X^T w (sum over t) + per-t dl^2 partials ========
        {
            int k0 = warp << 2;
            float sk0 = 0.f, sk1 = 0.f, sk2 = 0.f, sk3 = 0.f;
#pragma unroll
            for (int t = 0; t < 3; t++) {
                ull d0 = 0, d1 = 0;
                for (int r = 0; r < NUMR; r++) {
                    ulonglong2 xp = *(const ulonglong2*)&sm[OFF_X + (t * NUMR + r) * 32 + k0];
                    ull w = pack2(sm[OFF_W + t * 2400 + r * 24 + lane]);
                    fma2(d0, xp.x, w);
                    fma2(d1, xp.y, w);
                }
                float a, b, c, d;
                unpack2(a, b, d0); unpack2(c, d, d1);
                if (lane < 24)
                    sm[OFF_PART + ((6 + t) * 8 + warp) * 25 + lane] =
                        a * a + b * b + c * c + d * d;
                sk0 += a; sk1 += b; sk2 += c; sk3 += d;
            }
            if (lane < 24) {
                int base = OFF_DL + lane * 36 + k0;
                sm[base] = sk0; sm[base+1] = sk1; sm[base+2] = sk2; sm[base+3] = sk3;
            }
        }
        __syncthreads();   // DL + dln partials ready

        // ======== F: lsum update, sdl, norms ========
#pragma unroll
        for (int m = 0; m < 3; m++) {
            float sd = sm[OFF_DL + (col0 + m) * 36 + lane];
            lsum[m] -= sd;
            sdl[m] = sd;
        }

        float red[10];
#pragma unroll
        for (int q = 0; q < 9; q++) {
            float v = 0.f;
            if (lane < 8) {
                int base = OFF_PART + (q * 8 + lane) * 25 + col0;
                v = sm[base] + sm[base + 1] + sm[base + 2];
            }
            red[q] = v;
        }
        red[9] = dc;

#pragma unroll
        for (int off = 16; off; off >>= 1)
#pragma unroll
            for (int q = 0; q < 10; q++)
                red[q] += __shfl_xor_sync(0xffffffffu, red[q], off);

        if (lane == 0) {
#pragma unroll
            for (int q = 0; q < 10; q++)
                sm[OFF_RED + warp * 12 + q] = red[q];
        }
        __syncthreads();
        {
            int wp = warp ^ 1;
            float tot[10];
#pragma unroll
            for (int q = 0; q < 10; q++)
                tot[q] = sm[OFF_RED + warp * 12 + q] + sm[OFF_RED + wp * 12 + q];
            rp_sum += sqrtf(tot[0]) + sqrtf(tot[1]) + sqrtf(tot[2]);
            fp_sum += sqrtf(tot[3]) + sqrtf(tot[4]) + sqrtf(tot[5])
                    + sqrtf(tot[6]) + sqrtf(tot[7]) + sqrtf(tot[8]) + sqrtf(tot[9]);
        }
    }

    // ---- outputs ----
#pragma unroll
    for (int m = 0; m < 3; m++)
        out[s * NVAR + (mb + m) * 32 + lane] = cprev[m];
    if (h == 0 && lane == 0) {
        out[BATCH * NVAR + s]         = fp_sum * (1.0f / MAXIT);
        out[BATCH * NVAR + BATCH + s] = rp_sum * (1.0f / MAXIT);
    }
}

extern "C" void kernel_launch(void* const* d_in, const int* in_sizes, int n_in,
                              void* d_out, int out_size)
{
    const float* lamda = (const float*)d_in[0];
    const float* c_in  = (const float*)d_in[1];
    const float* c_s   = (const float*)d_in[2];
    const float* b_eq  = (const float*)d_in[3];
    const float* Av    = (const float*)d_in[4];
    const float* Aa    = (const float*)d_in[5];
    const float* Ap    = (const float*)d_in[6];
    const float* Qi    = (const float*)d_in[7];
    float* out = (float*)d_out;

    qprep_kernel<<<(NVAR * NVAR + 255) / 256, 256>>>(Qi);

    int smem_bytes = SMEM_FLOATS * sizeof(float);
    cudaFuncSetAttribute(proj_filter_kernel,
                         cudaFuncAttributeMaxDynamicSharedMemorySize, smem_bytes);
    proj_filter_kernel<<<BATCH / SPB, NTHREADS, smem_bytes>>>(
        lamda, c_in, c_s, b_eq, Av, Aa, Ap, Qi, out);
}

// round 8
// speedup vs baseline: 1.4496x; 1.4496x over previous
#include <cuda_runtime.h>
#include <math.h>

#define NUMR    100
#define BATCH   2048
#define NVAR    192
#define NEQC    30
#define NHDIM   222
#define MAXIT   15
#define SPB     8
#define NTHREADS 512

// shared memory float offsets
#define OFF_X    0        // 300*32 = 9600
#define OFF_Y    9600     // 3*100*48 = 14400
#define OFF_W    24000    // 14400
#define OFF_P    38400    // 48*36 = 1728
#define OFF_RHS  40128    // 8*196 = 1568
#define OFF_DLP  41696    // 6*32*49 = 9408  ([t*2+rhalf][k][col], stride 49)
#define OFF_PART 51104    // 6*16*49 = 4704
#define OFF_G    55808    // 1024
#define OFF_RED  56832    // 16*12 = 192
#define SMEM_FLOATS 57024 // 228,096 bytes

typedef unsigned long long ull;

__device__ __align__(16) float Qpad[NVAR * NVAR];

__device__ __forceinline__ void fma2(ull& d, ull a, ull b) {
    asm("fma.rn.f32x2 %0, %1, %2, %0;" : "+l"(d) : "l"(a), "l"(b));
}
__device__ __forceinline__ float hadd2(ull v) {
    float lo, hi;
    asm("mov.b64 {%0, %1}, %2;" : "=f"(lo), "=f"(hi) : "l"(v));
    return lo + hi;
}
__device__ __forceinline__ ull pack2(float v) {
    ull r; asm("mov.b64 %0, {%1, %1};" : "=l"(r) : "f"(v)); return r;
}
__device__ __forceinline__ void unpack2(float& lo, float& hi, ull v) {
    asm("mov.b64 {%0, %1}, %2;" : "=f"(lo), "=f"(hi) : "l"(v));
}

__global__ void qprep_kernel(const float* __restrict__ Qi)
{
    int idx = blockIdx.x * blockDim.x + threadIdx.x;
    if (idx < NVAR * NVAR) {
        int j = idx / NVAR;
        int k = idx - j * NVAR;
        Qpad[idx] = Qi[j * NHDIM + k];
    }
}

__global__ void __launch_bounds__(NTHREADS, 1)
proj_filter_kernel(const float* __restrict__ lamda,
                   const float* __restrict__ c_in_g,
                   const float* __restrict__ c_samp,
                   const float* __restrict__ b_eq,
                   const float* __restrict__ Av,
                   const float* __restrict__ Aa,
                   const float* __restrict__ Ap,
                   const float* __restrict__ Qi,
                   float* __restrict__ out)
{
    extern __shared__ float sm[];
    const int tid   = threadIdx.x;
    const int warp  = tid >> 5;
    const int lane  = tid & 31;
    const int samp  = warp >> 1;
    const int h     = warp & 1;
    const int mb    = 3 * h;
    const int s     = blockIdx.x * SPB + samp;
    const int col0  = samp * 6 + mb;

    // phase-B role
    const int bs  = lane & 7;
    const int br  = lane >> 3;
    const int bj0 = warp * 12 + br;

    // phase-E role: 12 active warps = t(3) x khalf(2) x rhalf(2)
    const int et  = warp >> 2;            // t (valid for warp<12)
    const int ekh = warp & 1;             // k-half: 16 k at offset 16*ekh
    const int erh = (warp >> 1) & 1;      // r-half: rows [50*erh, 50*erh+50)

    const float Vb[3] = {0.8f, 1.8f, 3.14159265358979323846f};

    // ---- stage X (300 rows x 32) ----
    for (int idx = tid; idx < 300 * 32; idx += NTHREADS) {
        int t   = idx / 3200;
        int rem = idx - t * 3200;
        int r = rem >> 5;
        int c = rem & 31;
        const float* Asrc = (t == 0) ? Av : ((t == 1) ? Aa : Ap);
        sm[OFF_X + (t * NUMR + r) * 32 + c] = Asrc[r * NVAR + c];
    }
    __syncthreads();

    // ---- G = sum_t X_t^T X_t ----
    {
        int a = warp;
        int b = lane;
        float g0 = 0.f, g1 = 0.f;
        for (int g = 0; g < 300; g++) {
            float xb  = sm[OFF_X + g * 32 + b];
            g0 += sm[OFF_X + g * 32 + a] * xb;
            g1 += sm[OFF_X + g * 32 + a + 16] * xb;
        }
        sm[OFF_G + a * 32 + b]        = g0;
        sm[OFF_G + (a + 16) * 32 + b] = g1;
    }

    // ---- per-sample state (lambda kept only as sum over t) ----
    float cin[3], cprev[3], lsum[3], sdl[3], pbq[3];
#pragma unroll
    for (int m = 0; m < 3; m++) {
        int j = (mb + m) * 32 + lane;
        cin[m]   = c_in_g[s * NVAR + j];
        cprev[m] = c_samp[s * NVAR + j];
        const float* lp = lamda + s * (3 * NVAR) + j;
        lsum[m] = lp[0] + lp[NVAR] + lp[2 * NVAR];
    }

#pragma unroll
    for (int jg = 0; jg < 3; jg++) {
        int j = bj0 + jg * 4;
        float a = 0.f;
        const float* bq = b_eq + (blockIdx.x * SPB + bs) * NEQC;
        for (int k = 0; k < NEQC; k++)
            a += Qi[j * NHDIM + NVAR + k] * bq[k];
        pbq[jg] = a;
    }

    // stage initial P (p0 = c_samp)
#pragma unroll
    for (int m = 0; m < 3; m++)
        sm[OFF_P + (col0 + m) * 36 + lane] = cprev[m];
    __syncthreads();   // X, G, P ready

    // ---- D0: y0/w0 (row-parallel over 48 cols) ----
    {
        ull PA[16], PB[16];
        const ulonglong2* PcA = (const ulonglong2*)&sm[OFF_P + lane * 36];
        const ulonglong2* PcB = (const ulonglong2*)&sm[OFF_P + (32 + (lane & 15)) * 36];
#pragma unroll
        for (int q = 0; q < 8; q++) {
            ulonglong2 a = PcA[q]; PA[2*q] = a.x; PA[2*q+1] = a.y;
            ulonglong2 b = PcB[q]; PB[2*q] = b.x; PB[2*q+1] = b.y;
        }
#pragma unroll
        for (int t = 0; t < 3; t++) {
            float V = Vb[t];
#pragma unroll
            for (int i = 0; i < 7; i++) {
                int r = warp + 16 * i;
                if (r < NUMR) {
                    const ulonglong2* Xr = (const ulonglong2*)&sm[OFF_X + (t * NUMR + r) * 32];
                    ull aA = 0, aB = 0;
#pragma unroll
                    for (int q = 0; q < 8; q++) {
                        ulonglong2 x = Xr[q];
                        fma2(aA, x.x, PA[2*q]); fma2(aA, x.y, PA[2*q+1]);
                        fma2(aB, x.x, PB[2*q]); fma2(aB, x.y, PB[2*q+1]);
                    }
                    float ynA = hadd2(aA), ynB = hadd2(aB);
                    int base = t * 4800 + r * 48;
                    sm[OFF_Y + base + lane] = ynA;
                    sm[OFF_W + base + lane] = fmaxf(ynA - V, 0.f) - fmaxf(-ynA - V, 0.f);
                    if (lane < 16) {
                        sm[OFF_Y + base + 32 + lane] = ynB;
                        sm[OFF_W + base + 32 + lane] = fmaxf(ynB - V, 0.f) - fmaxf(-ynB - V, 0.f);
                    }
                }
            }
        }
    }
    __syncthreads();

    // ---- E0: dl0 partials into DLP ----
    if (warp < 12) {
        ull dA[8] = {0,0,0,0,0,0,0,0}, dB[8] = {0,0,0,0,0,0,0,0};
        for (int r = erh * 50; r < erh * 50 + 50; r++) {
            const ulonglong2* Xp = (const ulonglong2*)&sm[OFF_X + (et * NUMR + r) * 32 + ekh * 16];
            int wbase = OFF_W + et * 4800 + r * 48;
            ull wA = pack2(sm[wbase + lane]);
            ull wB = pack2(sm[wbase + 32 + (lane & 15)]);
#pragma unroll
            for (int q = 0; q < 4; q++) {
                ulonglong2 x = Xp[q];
                fma2(dA[2*q], x.x, wA); fma2(dA[2*q+1], x.y, wA);
                fma2(dB[2*q], x.x, wB); fma2(dB[2*q+1], x.y, wB);
            }
        }
#pragma unroll
        for (int j = 0; j < 8; j++) {
            float lo, hi;
            int base = OFF_DLP + ((et * 2 + erh) * 32 + ekh * 16 + 2 * j) * 49;
            unpack2(lo, hi, dA[j]);
            sm[base + lane]      = lo;
            sm[base + 49 + lane] = hi;
            if (lane < 16) {
                unpack2(lo, hi, dB[j]);
                sm[base + 32 + lane]      = lo;
                sm[base + 49 + 32 + lane] = hi;
            }
        }
    }
    __syncthreads();

    // ---- sdl0 ----
#pragma unroll
    for (int m = 0; m < 3; m++) sdl[m] = 0.f;
#pragma unroll
    for (int t = 0; t < 3; t++)
#pragma unroll
        for (int m = 0; m < 3; m++)
            sdl[m] += sm[OFF_DLP + ((t * 2    ) * 32 + lane) * 49 + col0 + m]
                    + sm[OFF_DLP + ((t * 2 + 1) * 32 + lane) * 49 + col0 + m];

    float fp_sum = 0.f, rp_sum = 0.f;

    const int j0 = (bj0    ) * 48;
    const int j1 = (bj0 + 4) * 48;
    const int j2 = (bj0 + 8) * 48;

    for (int it = 0; it < MAXIT; it++) {
        // ======== A: gp = G@p ; rhs ========
        {
            const float* Gm = &sm[OFF_G];
            const float* P0 = &sm[OFF_P + col0 * 36];
            const float* P1 = P0 + 36;
            const float* P2 = P0 + 72;
            float g0 = 0.f, g1 = 0.f, g2 = 0.f;
#pragma unroll 8
            for (int k = 0; k < 32; k++) {
                float gk = Gm[k * 32 + lane];
                g0 += gk * P0[k]; g1 += gk * P1[k]; g2 += gk * P2[k];
            }
            float gpv[3] = {g0, g1, g2};
#pragma unroll
            for (int m = 0; m < 3; m++)
                sm[OFF_RHS + samp * 196 + (mb + m) * 32 + lane] =
                    lsum[m] + cin[m] + 2.f * gpv[m] - sdl[m];
        }
        __syncthreads();   // rhs ready

        // ======== B: primal = Qpad @ rhs + pb (L2-streamed, barrier-free) ========
        {
            const ulonglong2* Qp = (const ulonglong2*)Qpad;
            const ulonglong2* RV = (const ulonglong2*)&sm[OFF_RHS + bs * 196];
            ull a00 = 0, a01 = 0, a10 = 0, a11 = 0, a20 = 0, a21 = 0;
#pragma unroll 4
            for (int kk = 0; kk < 48; kk++) {
                ulonglong2 q0 = Qp[j0 + kk];
                ulonglong2 q1 = Qp[j1 + kk];
                ulonglong2 q2 = Qp[j2 + kk];
                ulonglong2 rv = RV[kk];
                fma2(a00, q0.x, rv.x); fma2(a01, q0.y, rv.y);
                fma2(a10, q1.x, rv.x); fma2(a11, q1.y, rv.y);
                fma2(a20, q2.x, rv.x); fma2(a21, q2.y, rv.y);
            }
            float p0 = hadd2(a00) + hadd2(a01) + pbq[0];
            float p1 = hadd2(a10) + hadd2(a11) + pbq[1];
            float p2 = hadd2(a20) + hadd2(a21) + pbq[2];
            int ja = bj0, jb = bj0 + 4, jc = bj0 + 8;
            sm[OFF_P + (bs * 6 + (ja >> 5)) * 36 + (ja & 31)] = p0;
            sm[OFF_P + (bs * 6 + (jb >> 5)) * 36 + (jb & 31)] = p1;
            sm[OFF_P + (bs * 6 + (jc >> 5)) * 36 + (jc & 31)] = p2;
        }
        __syncthreads();   // P_new ready

        // ======== C: dc ========
        float dc = 0.f;
#pragma unroll
        for (int m = 0; m < 3; m++) {
            float pr = sm[OFF_P + (col0 + m) * 36 + lane];
            float dd = pr - cprev[m];
            dc += dd * dd;
            cprev[m] = pr;
        }

        // ======== D: y/w update + res/ds partials (row-parallel) ========
        {
            ull PA[16], PB[16];
            const ulonglong2* PcA = (const ulonglong2*)&sm[OFF_P + lane * 36];
            const ulonglong2* PcB = (const ulonglong2*)&sm[OFF_P + (32 + (lane & 15)) * 36];
#pragma unroll
            for (int q = 0; q < 8; q++) {
                ulonglong2 a = PcA[q]; PA[2*q] = a.x; PA[2*q+1] = a.y;
                ulonglong2 b = PcB[q]; PB[2*q] = b.x; PB[2*q+1] = b.y;
            }
#pragma unroll
            for (int t = 0; t < 3; t++) {
                float V = Vb[t];
                float raA = 0.f, daA = 0.f, raB = 0.f, daB = 0.f;
#pragma unroll
                for (int i = 0; i < 7; i++) {
                    int r = warp + 16 * i;
                    if (r < NUMR) {
                        const ulonglong2* Xr = (const ulonglong2*)&sm[OFF_X + (t * NUMR + r) * 32];
                        ull aA = 0, aB = 0;
#pragma unroll
                        for (int q = 0; q < 8; q++) {
                            ulonglong2 x = Xr[q];
                            fma2(aA, x.x, PA[2*q]); fma2(aA, x.y, PA[2*q+1]);
                            fma2(aB, x.x, PB[2*q]); fma2(aB, x.y, PB[2*q+1]);
                        }
                        float ynA = hadd2(aA), ynB = hadd2(aB);
                        int base = t * 4800 + r * 48;
                        float yoA = sm[OFF_Y + base + lane];
                        float rtA = fmaxf(ynA - V, 0.f);
                        float rbA = fmaxf(-ynA - V, 0.f);
                        raA += rtA * rtA + rbA * rbA;
                        float d1 = fmaxf(V - ynA, 0.f) - fmaxf(V - yoA, 0.f);
                        float d2 = fmaxf(V + ynA, 0.f) - fmaxf(V + yoA, 0.f);
                        daA += d1 * d1 + d2 * d2;
                        sm[OFF_Y + base + lane] = ynA;
                        sm[OFF_W + base + lane] = rtA - rbA;
                        if (lane < 16) {
                            float yoB = sm[OFF_Y + base + 32 + lane];
                            float rtB = fmaxf(ynB - V, 0.f);
                            float rbB = fmaxf(-ynB - V, 0.f);
                            raB += rtB * rtB + rbB * rbB;
                            float e1 = fmaxf(V - ynB, 0.f) - fmaxf(V - yoB, 0.f);
                            float e2 = fmaxf(V + ynB, 0.f) - fmaxf(V + yoB, 0.f);
                            daB += e1 * e1 + e2 * e2;
                            sm[OFF_Y + base + 32 + lane] = ynB;
                            sm[OFF_W + base + 32 + lane] = rtB - rbB;
                        }
                    }
                }
                sm[OFF_PART + ((0 * 3 + t) * 16 + warp) * 49 + lane] = raA;
                sm[OFF_PART + ((1 * 3 + t) * 16 + warp) * 49 + lane] = daA;
                if (lane < 16) {
                    sm[OFF_PART + ((0 * 3 + t) * 16 + warp) * 49 + 32 + lane] = raB;
                    sm[OFF_PART + ((1 * 3 + t) * 16 + warp) * 49 + 32 + lane] = daB;
                }
            }
        }
        __syncthreads();   // W, res/ds partials ready

        // ======== E: dl partials (warp = t x khalf x rhalf, 16 k packed) ========
        if (warp < 12) {
            ull dA[8] = {0,0,0,0,0,0,0,0}, dB[8] = {0,0,0,0,0,0,0,0};
            for (int r = erh * 50; r < erh * 50 + 50; r++) {
                const ulonglong2* Xp = (const ulonglong2*)&sm[OFF_X + (et * NUMR + r) * 32 + ekh * 16];
                int wbase = OFF_W + et * 4800 + r * 48;
                ull wA = pack2(sm[wbase + lane]);
                ull wB = pack2(sm[wbase + 32 + (lane & 15)]);
#pragma unroll
                for (int q = 0; q < 4; q++) {
                    ulonglong2 x = Xp[q];
                    fma2(dA[2*q], x.x, wA); fma2(dA[2*q+1], x.y, wA);
                    fma2(dB[2*q], x.x, wB); fma2(dB[2*q+1], x.y, wB);
                }
            }
#pragma unroll
            for (int j = 0; j < 8; j++) {
                float lo, hi;
                int base = OFF_DLP + ((et * 2 + erh) * 32 + ekh * 16 + 2 * j) * 49;
                unpack2(lo, hi, dA[j]);
                sm[base + lane]      = lo;
                sm[base + 49 + lane] = hi;
                if (lane < 16) {
                    unpack2(lo, hi, dB[j]);
                    sm[base + 32 + lane]      = lo;
                    sm[base + 49 + 32 + lane] = hi;
                }
            }
        }
        __syncthreads();   // DLP ready

        // ======== F: lsum update, sdl, norms ========
        float dln[3];
#pragma unroll
        for (int m = 0; m < 3; m++) sdl[m] = 0.f;
#pragma unroll
        for (int t = 0; t < 3; t++) {
            float dls = 0.f;
#pragma unroll
            for (int m = 0; m < 3; m++) {
                float dl = sm[OFF_DLP + ((t * 2    ) * 32 + lane) * 49 + col0 + m]
                         + sm[OFF_DLP + ((t * 2 + 1) * 32 + lane) * 49 + col0 + m];
                lsum[m] -= dl;
                sdl[m]  += dl;
                dls += dl * dl;
            }
            dln[t] = dls;
        }
        float rds[6];
#pragma unroll
        for (int q = 0; q < 6; q++) {
            float v = 0.f;
            if (lane < 16) {
                int base = OFF_PART + (q * 16 + lane) * 49 + col0;
                v = sm[base] + sm[base + 1] + sm[base + 2];
            }
            rds[q] = v;
        }

        float red[10] = {rds[0], rds[1], rds[2],
                         rds[3], rds[4], rds[5],
                         dln[0], dln[1], dln[2], dc};
#pragma unroll
        for (int off = 16; off; off >>= 1)
#pragma unroll
            for (int q = 0; q < 10; q++)
                red[q] += __shfl_xor_sync(0xffffffffu, red[q], off);

        if (lane == 0) {
#pragma unroll
            for (int q = 0; q < 10; q++)
                sm[OFF_RED + warp * 12 + q] = red[q];
        }
        __syncthreads();
        {
            int wp = warp ^ 1;
            float tot[10];
#pragma unroll
            for (int q = 0; q < 10; q++)
                tot[q] = sm[OFF_RED + warp * 12 + q] + sm[OFF_RED + wp * 12 + q];
            rp_sum += sqrtf(tot[0]) + sqrtf(tot[1]) + sqrtf(tot[2]);
            fp_sum += sqrtf(tot[3]) + sqrtf(tot[4]) + sqrtf(tot[5])
                    + sqrtf(tot[6]) + sqrtf(tot[7]) + sqrtf(tot[8]) + sqrtf(tot[9]);
        }
    }

    // ---- outputs ----
#pragma unroll
    for (int m = 0; m < 3; m++)
        out[s * NVAR + (mb + m) * 32 + lane] = cprev[m];
    if (h == 0 && lane == 0) {
        out[BATCH * NVAR + s]         = fp_sum * (1.0f / MAXIT);
        out[BATCH * NVAR + BATCH + s] = rp_sum * (1.0f / MAXIT);
    }
}

extern "C" void kernel_launch(void* const* d_in, const int* in_sizes, int n_in,
                              void* d_out, int out_size)
{
    const float* lamda = (const float*)d_in[0];
    const float* c_in  = (const float*)d_in[1];
    const float* c_s   = (const float*)d_in[2];
    const float* b_eq  = (const float*)d_in[3];
    const float* Av    = (const float*)d_in[4];
    const float* Aa    = (const float*)d_in[5];
    const float* Ap    = (const float*)d_in[6];
    const float* Qi    = (const float*)d_in[7];
    float* out = (float*)d_out;

    qprep_kernel<<<(NVAR * NVAR + 255) / 256, 256>>>(Qi);

    int smem_bytes = SMEM_FLOATS * sizeof(float);
    cudaFuncSetAttribute(proj_filter_kernel,
                         cudaFuncAttributeMaxDynamicSharedMemorySize, smem_bytes);
    proj_filter_kernel<<<BATCH / SPB, NTHREADS, smem_bytes>>>(
        lamda, c_in, c_s, b_eq, Av, Aa, Ap, Qi, out);
}

// round 10
// speedup vs baseline: 1.7951x; 1.2383x over previous
#include <cuda_runtime.h>
#include <math.h>

#define NUMR    100
#define BATCH   2048
#define NVAR    192
#define NEQC    30
#define NHDIM   222
#define MAXIT   15
#define SPB     8
#define NTHREADS 512

// shared memory float offsets (44992 floats = 179,968 B)
#define OFF_X    0        // 300*32 = 9600   [u][32]
#define OFF_Y    9600     // 300*48 = 14400  [u][48]
#define OFF_P    24000    // 48*36 = 1728    [col][36]
#define OFF_QS   25728    // 48*32 = 1536    [col][32]
#define OFF_M11  27264    // 1024 pair layout [k2][pos][2]
#define OFF_MG2  28288    // 1024
#define OFF_DLP  29312    // 6*32*49 = 9408  [slice*32+k][49]
#define OFF_PART 38720    // 8*16*49 = 6272  [kind][warp][col48] (6,7 = dc buffers)
#define SMEM_FLOATS 44992

typedef unsigned long long ull;

__device__ float M11Pg[1024];
__device__ float MG2Pg[1024];
__device__ float G2g[1024];

__device__ __forceinline__ void fma2(ull& d, ull a, ull b) {
    asm("fma.rn.f32x2 %0, %1, %2, %0;" : "+l"(d) : "l"(a), "l"(b));
}
__device__ __forceinline__ float hadd2(ull v) {
    float lo, hi;
    asm("mov.b64 {%0, %1}, %2;" : "=f"(lo), "=f"(hi) : "l"(v));
    return lo + hi;
}
__device__ __forceinline__ ull pack2(float v) {
    ull r; asm("mov.b64 %0, {%1, %1};" : "=l"(r) : "f"(v)); return r;
}
__device__ __forceinline__ void unpack2(float& lo, float& hi, ull v) {
    asm("mov.b64 {%0, %1}, %2;" : "=f"(lo), "=f"(hi) : "l"(v));
}

// prep1: G2 = 2 * sum_t X_t^T X_t
__global__ void prep_g(const float* __restrict__ Av,
                       const float* __restrict__ Aa,
                       const float* __restrict__ Ap)
{
    __shared__ float xs[9600];
    int tid = threadIdx.x;
    for (int idx = tid; idx < 9600; idx += 1024) {
        int t = idx / 3200;
        int rem = idx - t * 3200;
        const float* A = (t == 0) ? Av : ((t == 1) ? Aa : Ap);
        xs[idx] = A[(rem >> 5) * NVAR + (rem & 31)];
    }
    __syncthreads();
    int a = tid >> 5, b = tid & 31;
    float g = 0.f;
    for (int u = 0; u < 300; u++)
        g += xs[u * 32 + a] * xs[u * 32 + b];
    G2g[a * 32 + b] = 2.f * g;
}

// prep2: M11 (pair layout) and M11G2 = M11 @ G2 (pair layout)
__global__ void prep_m(const float* __restrict__ Qi)
{
    int tid = threadIdx.x;
    int pos = tid >> 5, k = tid & 31;
    float acc = 0.f;
    for (int j = 0; j < 32; j++)
        acc += Qi[pos * NHDIM + j] * G2g[j * 32 + k];
    int o = (k >> 1) * 64 + pos * 2 + (k & 1);
    MG2Pg[o] = acc;
    M11Pg[o] = Qi[pos * NHDIM + k];
}

__global__ void __launch_bounds__(NTHREADS, 1)
proj_filter_kernel(const float* __restrict__ lamda,
                   const float* __restrict__ c_in_g,
                   const float* __restrict__ c_samp,
                   const float* __restrict__ b_eq,
                   const float* __restrict__ Av,
                   const float* __restrict__ Aa,
                   const float* __restrict__ Ap,
                   const float* __restrict__ Qi,
                   float* __restrict__ out)
{
    extern __shared__ float sm[];
    const int tid   = threadIdx.x;
    const int warp  = tid >> 5;
    const int lane  = tid & 31;
    const int samp  = warp >> 1;
    const int h     = warp & 1;
    const int mb    = 3 * h;
    const int s     = blockIdx.x * SPB + samp;
    const int col0  = samp * 6 + mb;     // first owned column
    const int col0s = samp * 6;          // sample's first column

    // E role: kq = 8-k chunk, rq = 75-row quarter
    const int kq = warp & 3;
    const int rq = warp >> 2;
    // segment tables (rows split at t boundaries 100/200)
    const int s0_start[4] = {0, 75, 150, 225};
    const int s0_len[4]   = {75, 25, 50, 75};
    const int s0_slice[4] = {0, 1, 3, 5};
    const int s0_t[4]     = {0, 0, 1, 2};
    const int s1_len[4]   = {0, 50, 25, 0};
    const int s1_slice[4] = {0, 2, 4, 0};
    const int s1_t[4]     = {0, 1, 2, 0};

    const float Vb[3] = {0.8f, 1.8f, 3.14159265358979323846f};

    // ---- stage X and the two 32x32 matrices ----
    for (int idx = tid; idx < 9600; idx += NTHREADS) {
        int t = idx / 3200;
        int rem = idx - t * 3200;
        const float* A = (t == 0) ? Av : ((t == 1) ? Aa : Ap);
        sm[OFF_X + idx] = A[(rem >> 5) * NVAR + (rem & 31)];
    }
    for (int idx = tid; idx < 2048; idx += NTHREADS) {
        if (idx < 1024) sm[OFF_M11 + idx] = M11Pg[idx];
        else            sm[OFF_MG2 + idx - 1024] = MG2Pg[idx - 1024];
    }

    // ---- per-sample state ----
    float cin[3], cprev[3], lsum[3], sdl[3], pbv[3];
#pragma unroll
    for (int m = 0; m < 3; m++) {
        int j = (mb + m) * 32 + lane;
        cin[m]   = c_in_g[s * NVAR + j];
        cprev[m] = c_samp[s * NVAR + j];
        const float* lp = lamda + s * (3 * NVAR) + j;
        lsum[m] = lp[0] + lp[NVAR] + lp[2 * NVAR];
        // pbv = M12 @ beq_m  (M12 = Q_inv[:32, 192:197])
        float a = 0.f;
        const float* bq = b_eq + s * NEQC + (mb + m) * 5;
#pragma unroll
        for (int k = 0; k < 5; k++)
            a += Qi[lane * NHDIM + NVAR + k] * bq[k];
        pbv[m] = a;
    }

    // stage p0
#pragma unroll
    for (int m = 0; m < 3; m++)
        sm[OFF_P + (col0 + m) * 36 + lane] = cprev[m];
    __syncthreads();   // X, M11, MG2, P ready

    // ---- D0: y0 (flattened rows, no norms) ----
    {
        ull PA[16], PB[16];
        const ulonglong2* PcA = (const ulonglong2*)&sm[OFF_P + lane * 36];
        const ulonglong2* PcB = (const ulonglong2*)&sm[OFF_P + (32 + (lane & 15)) * 36];
#pragma unroll
        for (int q = 0; q < 8; q++) {
            ulonglong2 a = PcA[q]; PA[2*q] = a.x; PA[2*q+1] = a.y;
            ulonglong2 b = PcB[q]; PB[2*q] = b.x; PB[2*q+1] = b.y;
        }
#pragma unroll
        for (int i = 0; i < 19; i++) {
            int u = warp + 16 * i;
            if (u < 300) {
                const ulonglong2* Xr = (const ulonglong2*)&sm[OFF_X + u * 32];
                ull aA = 0, aB = 0;
#pragma unroll
                for (int q = 0; q < 8; q++) {
                    ulonglong2 x = Xr[q];
                    fma2(aA, x.x, PA[2*q]); fma2(aA, x.y, PA[2*q+1]);
                    fma2(aB, x.x, PB[2*q]); fma2(aB, x.y, PB[2*q+1]);
                }
                sm[OFF_Y + u * 48 + lane] = hadd2(aA);
                if (lane < 16) sm[OFF_Y + u * 48 + 32 + lane] = hadd2(aB);
            }
        }
    }
    __syncthreads();

    // ---- E0: dl0 partials (w recomputed from y) ----
    for (int seg = 0; seg < 2; seg++) {
        int len   = seg ? s1_len[rq]   : s0_len[rq];
        if (len == 0) continue;
        int start = seg ? (s0_start[rq] + s0_len[rq]) : s0_start[rq];
        int slice = seg ? s1_slice[rq] : s0_slice[rq];
        int t     = seg ? s1_t[rq]     : s0_t[rq];
        float V = Vb[t];
        ull dA[4] = {0,0,0,0}, dB[4] = {0,0,0,0};
        for (int u = start; u < start + len; u++) {
            const ulonglong2* Xp = (const ulonglong2*)&sm[OFF_X + u * 32 + kq * 8];
            float yA = sm[OFF_Y + u * 48 + lane];
            float yB = sm[OFF_Y + u * 48 + 32 + (lane & 15)];
            ull wA = pack2(fmaxf(yA - V, 0.f) - fmaxf(-yA - V, 0.f));
            ull wB = pack2(fmaxf(yB - V, 0.f) - fmaxf(-yB - V, 0.f));
            ulonglong2 x0 = Xp[0], x1 = Xp[1];
            fma2(dA[0], x0.x, wA); fma2(dA[1], x0.y, wA);
            fma2(dA[2], x1.x, wA); fma2(dA[3], x1.y, wA);
            fma2(dB[0], x0.x, wB); fma2(dB[1], x0.y, wB);
            fma2(dB[2], x1.x, wB); fma2(dB[3], x1.y, wB);
        }
#pragma unroll
        for (int j = 0; j < 4; j++) {
            float lo, hi;
            int base = OFF_DLP + (slice * 32 + kq * 8 + 2 * j) * 49;
            unpack2(lo, hi, dA[j]);
            sm[base + lane] = lo;
            sm[base + 49 + lane] = hi;
            if (lane < 16) {
                unpack2(lo, hi, dB[j]);
                sm[base + 32 + lane] = lo;
                sm[base + 49 + 32 + lane] = hi;
            }
        }
    }
    __syncthreads();

    // ---- sdl0 ----
#pragma unroll
    for (int m = 0; m < 3; m++) sdl[m] = 0.f;
#pragma unroll
    for (int t = 0; t < 3; t++)
#pragma unroll
        for (int m = 0; m < 3; m++)
            sdl[m] += sm[OFF_DLP + ((2*t    ) * 32 + lane) * 49 + col0 + m]
                    + sm[OFF_DLP + ((2*t + 1) * 32 + lane) * 49 + col0 + m];

    float fp_sum = 0.f, rp_sum = 0.f;

    for (int it = 0; it < MAXIT; it++) {
        // ======== AB: p_new = M11*(lsum+cin-sdl) + M11G2*p + pb  (per-warp) ========
        float dc = 0.f;
        {
#pragma unroll
            for (int m = 0; m < 3; m++)
                sm[OFF_QS + (col0 + m) * 32 + lane] = lsum[m] + cin[m] - sdl[m];
            __syncwarp();
            ull acc0 = 0, acc1 = 0, acc2 = 0;
            const ull* M1 = (const ull*)&sm[OFF_M11];
            const ull* M2 = (const ull*)&sm[OFF_MG2];
            const ull* Q0 = (const ull*)&sm[OFF_QS + (col0    ) * 32];
            const ull* Q1 = (const ull*)&sm[OFF_QS + (col0 + 1) * 32];
            const ull* Q2 = (const ull*)&sm[OFF_QS + (col0 + 2) * 32];
            const ull* P0 = (const ull*)&sm[OFF_P  + (col0    ) * 36];
            const ull* P1 = (const ull*)&sm[OFF_P  + (col0 + 1) * 36];
            const ull* P2 = (const ull*)&sm[OFF_P  + (col0 + 2) * 36];
#pragma unroll 4
            for (int k2 = 0; k2 < 16; k2++) {
                ull mp = M1[k2 * 32 + lane];
                ull gp = M2[k2 * 32 + lane];
                fma2(acc0, mp, Q0[k2]); fma2(acc0, gp, P0[k2]);
                fma2(acc1, mp, Q1[k2]); fma2(acc1, gp, P1[k2]);
                fma2(acc2, mp, Q2[k2]); fma2(acc2, gp, P2[k2]);
            }
            float pn[3];
            pn[0] = hadd2(acc0) + pbv[0];
            pn[1] = hadd2(acc1) + pbv[1];
            pn[2] = hadd2(acc2) + pbv[2];
#pragma unroll
            for (int m = 0; m < 3; m++) {
                float dd = pn[m] - cprev[m];
                dc += dd * dd;
                cprev[m] = pn[m];
                sm[OFF_P + (col0 + m) * 36 + lane] = pn[m];
            }
            sm[OFF_PART + ((6 + (it & 1)) * 16 + warp) * 49 + lane] = dc;
        }
        __syncthreads();   // P_new ready                                  [bar1]

        // ======== D: y update + res/ds partials (flattened row-parallel) ========
        {
            ull PA[16], PB[16];
            const ulonglong2* PcA = (const ulonglong2*)&sm[OFF_P + lane * 36];
            const ulonglong2* PcB = (const ulonglong2*)&sm[OFF_P + (32 + (lane & 15)) * 36];
#pragma unroll
            for (int q = 0; q < 8; q++) {
                ulonglong2 a = PcA[q]; PA[2*q] = a.x; PA[2*q+1] = a.y;
                ulonglong2 b = PcB[q]; PB[2*q] = b.x; PB[2*q+1] = b.y;
            }
            float ra0A = 0.f, ra1A = 0.f, ra2A = 0.f;
            float da0A = 0.f, da1A = 0.f, da2A = 0.f;
            float ra0B = 0.f, ra1B = 0.f, ra2B = 0.f;
            float da0B = 0.f, da1B = 0.f, da2B = 0.f;
#pragma unroll
            for (int i = 0; i < 19; i++) {
                int u = warp + 16 * i;
                if (u < 300) {
                    int t = (u >= 100) + (u >= 200);
                    float V = Vb[t];
                    const ulonglong2* Xr = (const ulonglong2*)&sm[OFF_X + u * 32];
                    ull aA = 0, aB = 0;
#pragma unroll
                    for (int q = 0; q < 8; q++) {
                        ulonglong2 x = Xr[q];
                        fma2(aA, x.x, PA[2*q]); fma2(aA, x.y, PA[2*q+1]);
                        fma2(aB, x.x, PB[2*q]); fma2(aB, x.y, PB[2*q+1]);
                    }
                    float ynA = hadd2(aA), ynB = hadd2(aB);
                    float yoA = sm[OFF_Y + u * 48 + lane];
                    float yoB = sm[OFF_Y + u * 48 + 32 + (lane & 15)];
                    float rtA = fmaxf(ynA - V, 0.f), rbA = fmaxf(-ynA - V, 0.f);
                    float rtB = fmaxf(ynB - V, 0.f), rbB = fmaxf(-ynB - V, 0.f);
                    float rrA = rtA * rtA + rbA * rbA;
                    float d1 = fmaxf(V - ynA, 0.f) - fmaxf(V - yoA, 0.f);
                    float d2 = fmaxf(V + ynA, 0.f) - fmaxf(V + yoA, 0.f);
                    float ddA = d1 * d1 + d2 * d2;
                    float rrB = rtB * rtB + rbB * rbB;
                    float e1 = fmaxf(V - ynB, 0.f) - fmaxf(V - yoB, 0.f);
                    float e2 = fmaxf(V + ynB, 0.f) - fmaxf(V + yoB, 0.f);
                    float ddB = e1 * e1 + e2 * e2;
                    if (t == 0)      { ra0A += rrA; da0A += ddA; ra0B += rrB; da0B += ddB; }
                    else if (t == 1) { ra1A += rrA; da1A += ddA; ra1B += rrB; da1B += ddB; }
                    else             { ra2A += rrA; da2A += ddA; ra2B += rrB; da2B += ddB; }
                    sm[OFF_Y + u * 48 + lane] = ynA;
                    if (lane < 16) sm[OFF_Y + u * 48 + 32 + lane] = ynB;
                }
            }
            // PART indexed by COLUMN: A-set cols 0..31 at +lane, B-set cols 32..47 at +32+lane
            sm[OFF_PART + ((0 * 3 + 0) * 16 + warp) * 49 + lane] = ra0A;
            sm[OFF_PART + ((0 * 3 + 1) * 16 + warp) * 49 + lane] = ra1A;
            sm[OFF_PART + ((0 * 3 + 2) * 16 + warp) * 49 + lane] = ra2A;
            sm[OFF_PART + ((1 * 3 + 0) * 16 + warp) * 49 + lane] = da0A;
            sm[OFF_PART + ((1 * 3 + 1) * 16 + warp) * 49 + lane] = da1A;
            sm[OFF_PART + ((1 * 3 + 2) * 16 + warp) * 49 + lane] = da2A;
            if (lane < 16) {
                sm[OFF_PART + ((0 * 3 + 0) * 16 + warp) * 49 + 32 + lane] = ra0B;
                sm[OFF_PART + ((0 * 3 + 1) * 16 + warp) * 49 + 32 + lane] = ra1B;
                sm[OFF_PART + ((0 * 3 + 2) * 16 + warp) * 49 + 32 + lane] = ra2B;
                sm[OFF_PART + ((1 * 3 + 0) * 16 + warp) * 49 + 32 + lane] = da0B;
                sm[OFF_PART + ((1 * 3 + 1) * 16 + warp) * 49 + 32 + lane] = da1B;
                sm[OFF_PART + ((1 * 3 + 2) * 16 + warp) * 49 + 32 + lane] = da2B;
            }
        }
        __syncthreads();   // Y, partials ready                            [bar2]

        // ======== E: dl partials (16 warps, w recomputed from y) ========
        for (int seg = 0; seg < 2; seg++) {
            int len   = seg ? s1_len[rq]   : s0_len[rq];
            if (len == 0) continue;
            int start = seg ? (s0_start[rq] + s0_len[rq]) : s0_start[rq];
            int slice = seg ? s1_slice[rq] : s0_slice[rq];
            int t     = seg ? s1_t[rq]     : s0_t[rq];
            float V = Vb[t];
            ull dA[4] = {0,0,0,0}, dB[4] = {0,0,0,0};
            for (int u = start; u < start + len; u++) {
                const ulonglong2* Xp = (const ulonglong2*)&sm[OFF_X + u * 32 + kq * 8];
                float yA = sm[OFF_Y + u * 48 + lane];
                float yB = sm[OFF_Y + u * 48 + 32 + (lane & 15)];
                ull wA = pack2(fmaxf(yA - V, 0.f) - fmaxf(-yA - V, 0.f));
                ull wB = pack2(fmaxf(yB - V, 0.f) - fmaxf(-yB - V, 0.f));
                ulonglong2 x0 = Xp[0], x1 = Xp[1];
                fma2(dA[0], x0.x, wA); fma2(dA[1], x0.y, wA);
                fma2(dA[2], x1.x, wA); fma2(dA[3], x1.y, wA);
                fma2(dB[0], x0.x, wB); fma2(dB[1], x0.y, wB);
                fma2(dB[2], x1.x, wB); fma2(dB[3], x1.y, wB);
            }
#pragma unroll
            for (int j = 0; j < 4; j++) {
                float lo, hi;
                int base = OFF_DLP + (slice * 32 + kq * 8 + 2 * j) * 49;
                unpack2(lo, hi, dA[j]);
                sm[base + lane] = lo;
                sm[base + 49 + lane] = hi;
                if (lane < 16) {
                    unpack2(lo, hi, dB[j]);
                    sm[base + 32 + lane] = lo;
                    sm[base + 49 + 32 + lane] = hi;
                }
            }
        }
        __syncthreads();   // DLP ready                                    [bar3]

        // ======== F: lsum/sdl update + full-sample norms ========
        float red[10];
#pragma unroll
        for (int m = 0; m < 3; m++) sdl[m] = 0.f;
#pragma unroll
        for (int t = 0; t < 3; t++) {
            float dls = 0.f;
#pragma unroll
            for (int c = 0; c < 6; c++) {
                float dl = sm[OFF_DLP + ((2*t    ) * 32 + lane) * 49 + col0s + c]
                         + sm[OFF_DLP + ((2*t + 1) * 32 + lane) * 49 + col0s + c];
                dls += dl * dl;
                if (c >= mb && c < mb + 3) {
                    lsum[c - mb] -= dl;
                    sdl[c - mb]  += dl;
                }
            }
            red[6 + t] = dls;
        }
#pragma unroll
        for (int q = 0; q < 6; q++) {
            float v = 0.f;
            if (lane < 16) {
                const float* pb_ = &sm[OFF_PART + (q * 16 + lane) * 49 + col0s];
                v = pb_[0] + pb_[1] + pb_[2] + pb_[3] + pb_[4] + pb_[5];
            }
            red[q] = v;
        }
        red[9] = sm[OFF_PART + ((6 + (it & 1)) * 16 + warp) * 49 + lane]
               + sm[OFF_PART + ((6 + (it & 1)) * 16 + (warp ^ 1)) * 49 + lane];

#pragma unroll
        for (int off = 16; off; off >>= 1)
#pragma unroll
            for (int q = 0; q < 10; q++)
                red[q] += __shfl_xor_sync(0xffffffffu, red[q], off);

        rp_sum += sqrtf(red[0]) + sqrtf(red[1]) + sqrtf(red[2]);
        fp_sum += sqrtf(red[3]) + sqrtf(red[4]) + sqrtf(red[5])
                + sqrtf(red[6]) + sqrtf(red[7]) + sqrtf(red[8]) + sqrtf(red[9]);
        // no barrier: next AB writes only warp-local QS/P-cols and the OTHER dc buffer
    }

    // ---- outputs ----
#pragma unroll
    for (int m = 0; m < 3; m++)
        out[s * NVAR + (mb + m) * 32 + lane] = cprev[m];
    if (h == 0 && lane == 0) {
        out[BATCH * NVAR + s]         = fp_sum * (1.0f / MAXIT);
        out[BATCH * NVAR + BATCH + s] = rp_sum * (1.0f / MAXIT);
    }
}

extern "C" void kernel_launch(void* const* d_in, const int* in_sizes, int n_in,
                              void* d_out, int out_size)
{
    const float* lamda = (const float*)d_in[0];
    const float* c_in  = (const float*)d_in[1];
    const float* c_s   = (const float*)d_in[2];
    const float* b_eq  = (const float*)d_in[3];
    const float* Av    = (const float*)d_in[4];
    const float* Aa    = (const float*)d_in[5];
    const float* Ap    = (const float*)d_in[6];
    const float* Qi    = (const float*)d_in[7];
    float* out = (float*)d_out;

    prep_g<<<1, 1024>>>(Av, Aa, Ap);
    prep_m<<<1, 1024>>>(Qi);

    int smem_bytes = SMEM_FLOATS * sizeof(float);
    cudaFuncSetAttribute(proj_filter_kernel,
                         cudaFuncAttributeMaxDynamicSharedMemorySize, smem_bytes);
    proj_filter_kernel<<<BATCH / SPB, NTHREADS, smem_bytes>>>(
        lamda, c_in, c_s, b_eq, Av, Aa, Ap, Qi, out);
}

// round 11
// speedup vs baseline: 1.9505x; 1.0865x over previous
#include <cuda_runtime.h>
#include <math.h>

#define NUMR    100
#define BATCH   2048
#define NVAR    192
#define NEQC    30
#define NHDIM   222
#define MAXIT   15
#define SPB     8
#define NTHREADS 512
#define PIF     3.14159265358979323846f

// shared memory float offsets (54688 floats = 218,752 B)
#define OFF_X    0        // 300*32 = 9600   [u][32]
#define OFF_Y    9600     // 300*48 = 14400  [u][48]
#define OFF_W    24000    // 300*48 = 14400  [u][48]
#define OFF_P    38400    // 48*36 = 1728
#define OFF_QS   40128    // 48*32 = 1536
#define OFF_M11  41664    // 1024 pair layout
#define OFF_MG2  42688    // 1024
#define OFF_DLP  43712    // 3*32*49 = 4704  [t*32+k][49]
#define OFF_PART 48416    // 8*16*49 = 6272  (6,7 = dc buffers)
#define SMEM_FLOATS 54688

typedef unsigned long long ull;

__device__ float M11Pg[1024];
__device__ float MG2Pg[1024];
__device__ float G2g[1024];

__device__ __forceinline__ void fma2(ull& d, ull a, ull b) {
    asm("fma.rn.f32x2 %0, %1, %2, %0;" : "+l"(d) : "l"(a), "l"(b));
}
__device__ __forceinline__ float hadd2(ull v) {
    float lo, hi;
    asm("mov.b64 {%0, %1}, %2;" : "=f"(lo), "=f"(hi) : "l"(v));
    return lo + hi;
}
__device__ __forceinline__ ull pack2(float v) {
    ull r; asm("mov.b64 %0, {%1, %1};" : "=l"(r) : "f"(v)); return r;
}
__device__ __forceinline__ void unpack2(float& lo, float& hi, ull v) {
    asm("mov.b64 {%0, %1}, %2;" : "=f"(lo), "=f"(hi) : "l"(v));
}

// prep1: G2 = 2 * sum_t X_t^T X_t
__global__ void prep_g(const float* __restrict__ Av,
                       const float* __restrict__ Aa,
                       const float* __restrict__ Ap)
{
    __shared__ float xs[9600];
    int tid = threadIdx.x;
    for (int idx = tid; idx < 9600; idx += 1024) {
        int t = idx / 3200;
        int rem = idx - t * 3200;
        const float* A = (t == 0) ? Av : ((t == 1) ? Aa : Ap);
        xs[idx] = A[(rem >> 5) * NVAR + (rem & 31)];
    }
    __syncthreads();
    int a = tid >> 5, b = tid & 31;
    float g = 0.f;
#pragma unroll 4
    for (int u = 0; u < 300; u++)
        g += xs[u * 32 + a] * xs[u * 32 + b];
    G2g[a * 32 + b] = 2.f * g;
}

// prep2: M11 (pair layout) and M11G2 = M11 @ G2 (pair layout)
__global__ void prep_m(const float* __restrict__ Qi)
{
    int tid = threadIdx.x;
    int pos = tid >> 5, k = tid & 31;
    float acc = 0.f;
#pragma unroll 4
    for (int j = 0; j < 32; j++)
        acc += Qi[pos * NHDIM + j] * G2g[j * 32 + k];
    int o = (k >> 1) * 64 + pos * 2 + (k & 1);
    MG2Pg[o] = acc;
    M11Pg[o] = Qi[pos * NHDIM + k];
}

__global__ void __launch_bounds__(NTHREADS, 1)
proj_filter_kernel(const float* __restrict__ lamda,
                   const float* __restrict__ c_in_g,
                   const float* __restrict__ c_samp,
                   const float* __restrict__ b_eq,
                   const float* __restrict__ Av,
                   const float* __restrict__ Aa,
                   const float* __restrict__ Ap,
                   const float* __restrict__ Qi,
                   float* __restrict__ out)
{
    extern __shared__ float sm[];
    const int tid   = threadIdx.x;
    const int warp  = tid >> 5;
    const int lane  = tid & 31;
    const int samp  = warp >> 1;
    const int h     = warp & 1;
    const int mb    = 3 * h;
    const int s     = blockIdx.x * SPB + samp;
    const int col0  = samp * 6 + mb;
    const int col0s = samp * 6;

    // E role (warp<12): t block, kq 8-k chunk
    const int et = warp >> 2;
    const int kq = warp & 3;

    // ---- stage X and the two 32x32 matrices ----
    for (int idx = tid; idx < 9600; idx += NTHREADS) {
        int t = idx / 3200;
        int rem = idx - t * 3200;
        const float* A = (t == 0) ? Av : ((t == 1) ? Aa : Ap);
        sm[OFF_X + idx] = A[(rem >> 5) * NVAR + (rem & 31)];
    }
    for (int idx = tid; idx < 2048; idx += NTHREADS) {
        if (idx < 1024) sm[OFF_M11 + idx] = M11Pg[idx];
        else            sm[OFF_MG2 + idx - 1024] = MG2Pg[idx - 1024];
    }

    // ---- per-sample state ----
    float cin[3], cprev[3], lsum[3], sdl[3], pbv[3];
#pragma unroll
    for (int m = 0; m < 3; m++) {
        int j = (mb + m) * 32 + lane;
        cin[m]   = c_in_g[s * NVAR + j];
        cprev[m] = c_samp[s * NVAR + j];
        const float* lp = lamda + s * (3 * NVAR) + j;
        lsum[m] = lp[0] + lp[NVAR] + lp[2 * NVAR];
        float a = 0.f;
        const float* bq = b_eq + s * NEQC + (mb + m) * 5;
#pragma unroll
        for (int k = 0; k < 5; k++)
            a += Qi[lane * NHDIM + NVAR + k] * bq[k];
        pbv[m] = a;
    }

#pragma unroll
    for (int m = 0; m < 3; m++)
        sm[OFF_P + (col0 + m) * 36 + lane] = cprev[m];
    __syncthreads();   // X, M11, MG2, P ready

    // ---- D0: y0 and w0 (simple single-pass shape; runs once) ----
    {
        ull PA[16], PB[16];
        const ulonglong2* PcA = (const ulonglong2*)&sm[OFF_P + lane * 36];
        const ulonglong2* PcB = (const ulonglong2*)&sm[OFF_P + (32 + (lane & 15)) * 36];
#pragma unroll
        for (int q = 0; q < 8; q++) {
            ulonglong2 a = PcA[q]; PA[2*q] = a.x; PA[2*q+1] = a.y;
            ulonglong2 b = PcB[q]; PB[2*q] = b.x; PB[2*q+1] = b.y;
        }
#pragma unroll
        for (int i = 0; i < 19; i++) {
            int u = warp + 16 * i;
            if (u < 300) {
                int t = (u >= 100) + (u >= 200);
                float V = (t == 0) ? 0.8f : ((t == 1) ? 1.8f : PIF);
                const ulonglong2* Xr = (const ulonglong2*)&sm[OFF_X + u * 32];
                ull aA = 0, aB = 0;
#pragma unroll
                for (int q = 0; q < 8; q++) {
                    ulonglong2 x = Xr[q];
                    fma2(aA, x.x, PA[2*q]); fma2(aA, x.y, PA[2*q+1]);
                    fma2(aB, x.x, PB[2*q]); fma2(aB, x.y, PB[2*q+1]);
                }
                float ynA = hadd2(aA), ynB = hadd2(aB);
                sm[OFF_Y + u * 48 + lane] = ynA;
                sm[OFF_W + u * 48 + lane] =
                    fmaxf(ynA - V, 0.f) - fmaxf(-ynA - V, 0.f);
                if (lane < 16) {
                    sm[OFF_Y + u * 48 + 32 + lane] = ynB;
                    sm[OFF_W + u * 48 + 32 + lane] =
                        fmaxf(ynB - V, 0.f) - fmaxf(-ynB - V, 0.f);
                }
            }
        }
    }
    __syncthreads();

    // ---- E0: dl0 partials from W ----
    if (warp < 12) {
        ull dA[4] = {0,0,0,0}, dB[4] = {0,0,0,0};
        for (int u = et * 100; u < et * 100 + 100; u++) {
            const ulonglong2* Xp = (const ulonglong2*)&sm[OFF_X + u * 32 + kq * 8];
            ull wA = pack2(sm[OFF_W + u * 48 + lane]);
            ull wB = pack2(sm[OFF_W + u * 48 + 32 + (lane & 15)]);
            ulonglong2 x0 = Xp[0], x1 = Xp[1];
            fma2(dA[0], x0.x, wA); fma2(dA[1], x0.y, wA);
            fma2(dA[2], x1.x, wA); fma2(dA[3], x1.y, wA);
            fma2(dB[0], x0.x, wB); fma2(dB[1], x0.y, wB);
            fma2(dB[2], x1.x, wB); fma2(dB[3], x1.y, wB);
        }
#pragma unroll
        for (int j = 0; j < 4; j++) {
            float lo, hi;
            int base = OFF_DLP + (et * 32 + kq * 8 + 2 * j) * 49;
            unpack2(lo, hi, dA[j]);
            sm[base + lane] = lo;
            sm[base + 49 + lane] = hi;
            if (lane < 16) {
                unpack2(lo, hi, dB[j]);
                sm[base + 32 + lane] = lo;
                sm[base + 49 + 32 + lane] = hi;
            }
        }
    }
    __syncthreads();

    // ---- sdl0 ----
#pragma unroll
    for (int m = 0; m < 3; m++) sdl[m] = 0.f;
#pragma unroll
    for (int t = 0; t < 3; t++)
#pragma unroll
        for (int m = 0; m < 3; m++)
            sdl[m] += sm[OFF_DLP + (t * 32 + lane) * 49 + col0 + m];

    float fp_sum = 0.f, rp_sum = 0.f;

    for (int it = 0; it < MAXIT; it++) {
        // ======== AB: p_new = M11*(lsum+cin-sdl) + M11G2*p + pb ========
        float dc = 0.f;
        {
#pragma unroll
            for (int m = 0; m < 3; m++)
                sm[OFF_QS + (col0 + m) * 32 + lane] = lsum[m] + cin[m] - sdl[m];
            __syncwarp();
            ull acc0 = 0, acc1 = 0, acc2 = 0;
            const ull* M1 = (const ull*)&sm[OFF_M11];
            const ull* M2 = (const ull*)&sm[OFF_MG2];
            const ull* Q0 = (const ull*)&sm[OFF_QS + (col0    ) * 32];
            const ull* Q1 = (const ull*)&sm[OFF_QS + (col0 + 1) * 32];
            const ull* Q2 = (const ull*)&sm[OFF_QS + (col0 + 2) * 32];
            const ull* P0 = (const ull*)&sm[OFF_P  + (col0    ) * 36];
            const ull* P1 = (const ull*)&sm[OFF_P  + (col0 + 1) * 36];
            const ull* P2 = (const ull*)&sm[OFF_P  + (col0 + 2) * 36];
#pragma unroll 4
            for (int k2 = 0; k2 < 16; k2++) {
                ull mp = M1[k2 * 32 + lane];
                ull gp = M2[k2 * 32 + lane];
                fma2(acc0, mp, Q0[k2]); fma2(acc0, gp, P0[k2]);
                fma2(acc1, mp, Q1[k2]); fma2(acc1, gp, P1[k2]);
                fma2(acc2, mp, Q2[k2]); fma2(acc2, gp, P2[k2]);
            }
            float pn[3];
            pn[0] = hadd2(acc0) + pbv[0];
            pn[1] = hadd2(acc1) + pbv[1];
            pn[2] = hadd2(acc2) + pbv[2];
#pragma unroll
            for (int m = 0; m < 3; m++) {
                float dd = pn[m] - cprev[m];
                dc += dd * dd;
                cprev[m] = pn[m];
                sm[OFF_P + (col0 + m) * 36 + lane] = pn[m];
            }
            sm[OFF_PART + ((6 + (it & 1)) * 16 + warp) * 49 + lane] = dc;
        }
        __syncthreads();   // P_new ready                                  [bar1]

        // ======== D: y/w update + res/ds partials ========
        {
            ull PA[16], PB[16];
            const ulonglong2* PcA = (const ulonglong2*)&sm[OFF_P + lane * 36];
            const ulonglong2* PcB = (const ulonglong2*)&sm[OFF_P + (32 + (lane & 15)) * 36];
#pragma unroll
            for (int q = 0; q < 8; q++) {
                ulonglong2 a = PcA[q]; PA[2*q] = a.x; PA[2*q+1] = a.y;
                ulonglong2 b = PcB[q]; PB[2*q] = b.x; PB[2*q+1] = b.y;
            }
            // ---- A-pass: cols 0-31, rows warp+16i ----
            float ra0A = 0.f, ra1A = 0.f, ra2A = 0.f;
            float da0A = 0.f, da1A = 0.f, da2A = 0.f;
#pragma unroll
            for (int i = 0; i < 19; i++) {
                int u = warp + 16 * i;
                if (u < 300) {
                    int t = (u >= 100) + (u >= 200);
                    float V = (t == 0) ? 0.8f : ((t == 1) ? 1.8f : PIF);
                    const ulonglong2* Xr = (const ulonglong2*)&sm[OFF_X + u * 32];
                    ull aA = 0;
#pragma unroll
                    for (int q = 0; q < 8; q++) {
                        ulonglong2 x = Xr[q];
                        fma2(aA, x.x, PA[2*q]); fma2(aA, x.y, PA[2*q+1]);
                    }
                    float yn = hadd2(aA);
                    float yo = sm[OFF_Y + u * 48 + lane];
                    float rt = fmaxf(yn - V, 0.f), rb = fmaxf(-yn - V, 0.f);
                    float rr = rt * rt + rb * rb;
                    float d1 = fmaxf(V - yn, 0.f) - fmaxf(V - yo, 0.f);
                    float d2 = fmaxf(V + yn, 0.f) - fmaxf(V + yo, 0.f);
                    float dd = d1 * d1 + d2 * d2;
                    if (t == 0)      { ra0A += rr; da0A += dd; }
                    else if (t == 1) { ra1A += rr; da1A += dd; }
                    else             { ra2A += rr; da2A += dd; }
                    sm[OFF_Y + u * 48 + lane] = yn;
                    sm[OFF_W + u * 48 + lane] = rt - rb;
                }
            }
            // ---- B-pass: cols 32-47, two rows per iter (per-half-warp) ----
            float ra0B = 0.f, ra1B = 0.f, ra2B = 0.f;
            float da0B = 0.f, da1B = 0.f, da2B = 0.f;
            int hoff = (lane >= 16) ? 16 : 0;
#pragma unroll
            for (int j = 0; j < 10; j++) {
                int u = warp + 32 * j + hoff;
                bool valid = (u < 300);
                int uc = valid ? u : 0;
                int t = (uc >= 100) + (uc >= 200);
                float V = (t == 0) ? 0.8f : ((t == 1) ? 1.8f : PIF);
                const ulonglong2* Xr = (const ulonglong2*)&sm[OFF_X + uc * 32];
                ull aB = 0;
#pragma unroll
                for (int q = 0; q < 8; q++) {
                    ulonglong2 x = Xr[q];
                    fma2(aB, x.x, PB[2*q]); fma2(aB, x.y, PB[2*q+1]);
                }
                float yn = hadd2(aB);
                int yaddr = OFF_Y + uc * 48 + 32 + (lane & 15);
                float yo = sm[yaddr];
                float rt = fmaxf(yn - V, 0.f), rb = fmaxf(-yn - V, 0.f);
                float rr = rt * rt + rb * rb;
                float d1 = fmaxf(V - yn, 0.f) - fmaxf(V - yo, 0.f);
                float d2 = fmaxf(V + yn, 0.f) - fmaxf(V + yo, 0.f);
                float dd = d1 * d1 + d2 * d2;
                if (valid) {
                    if (t == 0)      { ra0B += rr; da0B += dd; }
                    else if (t == 1) { ra1B += rr; da1B += dd; }
                    else             { ra2B += rr; da2B += dd; }
                    sm[yaddr] = yn;
                    sm[OFF_W + uc * 48 + 32 + (lane & 15)] = rt - rb;
                }
            }
            // fold B halves (rows differ per half; same column per lane&15)
            ra0B += __shfl_xor_sync(0xffffffffu, ra0B, 16);
            ra1B += __shfl_xor_sync(0xffffffffu, ra1B, 16);
            ra2B += __shfl_xor_sync(0xffffffffu, ra2B, 16);
            da0B += __shfl_xor_sync(0xffffffffu, da0B, 16);
            da1B += __shfl_xor_sync(0xffffffffu, da1B, 16);
            da2B += __shfl_xor_sync(0xffffffffu, da2B, 16);

            sm[OFF_PART + ((0 * 3 + 0) * 16 + warp) * 49 + lane] = ra0A;
            sm[OFF_PART + ((0 * 3 + 1) * 16 + warp) * 49 + lane] = ra1A;
            sm[OFF_PART + ((0 * 3 + 2) * 16 + warp) * 49 + lane] = ra2A;
            sm[OFF_PART + ((1 * 3 + 0) * 16 + warp) * 49 + lane] = da0A;
            sm[OFF_PART + ((1 * 3 + 1) * 16 + warp) * 49 + lane] = da1A;
            sm[OFF_PART + ((1 * 3 + 2) * 16 + warp) * 49 + lane] = da2A;
            if (lane < 16) {
                sm[OFF_PART + ((0 * 3 + 0) * 16 + warp) * 49 + 32 + lane] = ra0B;
                sm[OFF_PART + ((0 * 3 + 1) * 16 + warp) * 49 + 32 + lane] = ra1B;
                sm[OFF_PART + ((0 * 3 + 2) * 16 + warp) * 49 + 32 + lane] = ra2B;
                sm[OFF_PART + ((1 * 3 + 0) * 16 + warp) * 49 + 32 + lane] = da0B;
                sm[OFF_PART + ((1 * 3 + 1) * 16 + warp) * 49 + 32 + lane] = da1B;
                sm[OFF_PART + ((1 * 3 + 2) * 16 + warp) * 49 + 32 + lane] = da2B;
            }
        }
        __syncthreads();   // Y, W, partials ready                         [bar2]

        // ======== E: dl partials from W (12 warps; t block x 8-k chunk) ========
        if (warp < 12) {
            ull dA[4] = {0,0,0,0}, dB[4] = {0,0,0,0};
            for (int u = et * 100; u < et * 100 + 100; u++) {
                const ulonglong2* Xp = (const ulonglong2*)&sm[OFF_X + u * 32 + kq * 8];
                ull wA = pack2(sm[OFF_W + u * 48 + lane]);
                ull wB = pack2(sm[OFF_W + u * 48 + 32 + (lane & 15)]);
                ulonglong2 x0 = Xp[0], x1 = Xp[1];
                fma2(dA[0], x0.x, wA); fma2(dA[1], x0.y, wA);
                fma2(dA[2], x1.x, wA); fma2(dA[3], x1.y, wA);
                fma2(dB[0], x0.x, wB); fma2(dB[1], x0.y, wB);
                fma2(dB[2], x1.x, wB); fma2(dB[3], x1.y, wB);
            }
#pragma unroll
            for (int j = 0; j < 4; j++) {
                float lo, hi;
                int base = OFF_DLP + (et * 32 + kq * 8 + 2 * j) * 49;
                unpack2(lo, hi, dA[j]);
                sm[base + lane] = lo;
                sm[base + 49 + lane] = hi;
                if (lane < 16) {
                    unpack2(lo, hi, dB[j]);
                    sm[base + 32 + lane] = lo;
                    sm[base + 49 + 32 + lane] = hi;
                }
            }
        }
        __syncthreads();   // DLP ready                                    [bar3]

        // ======== F: lsum/sdl update + full-sample norms ========
        float red[10];
#pragma unroll
        for (int m = 0; m < 3; m++) sdl[m] = 0.f;
#pragma unroll
        for (int t = 0; t < 3; t++) {
            float dls = 0.f;
#pragma unroll
            for (int c = 0; c < 6; c++) {
                float dl = sm[OFF_DLP + (t * 32 + lane) * 49 + col0s + c];
                dls += dl * dl;
                if (c >= mb && c < mb + 3) {
                    lsum[c - mb] -= dl;
                    sdl[c - mb]  += dl;
                }
            }
            red[6 + t] = dls;
        }
#pragma unroll
        for (int q = 0; q < 6; q++) {
            float v = 0.f;
            if (lane < 16) {
                const float* pb_ = &sm[OFF_PART + (q * 16 + lane) * 49 + col0s];
                v = pb_[0] + pb_[1] + pb_[2] + pb_[3] + pb_[4] + pb_[5];
            }
            red[q] = v;
        }
        red[9] = sm[OFF_PART + ((6 + (it & 1)) * 16 + warp) * 49 + lane]
               + sm[OFF_PART + ((6 + (it & 1)) * 16 + (warp ^ 1)) * 49 + lane];

#pragma unroll
        for (int off = 16; off; off >>= 1)
#pragma unroll
            for (int q = 0; q < 10; q++)
                red[q] += __shfl_xor_sync(0xffffffffu, red[q], off);

        rp_sum += sqrtf(red[0]) + sqrtf(red[1]) + sqrtf(red[2]);
        fp_sum += sqrtf(red[3]) + sqrtf(red[4]) + sqrtf(red[5])
                + sqrtf(red[6]) + sqrtf(red[7]) + sqrtf(red[8]) + sqrtf(red[9]);
    }

    // ---- outputs ----
#pragma unroll
    for (int m = 0; m < 3; m++)
        out[s * NVAR + (mb + m) * 32 + lane] = cprev[m];
    if (h == 0 && lane == 0) {
        out[BATCH * NVAR + s]         = fp_sum * (1.0f / MAXIT);
        out[BATCH * NVAR + BATCH + s] = rp_sum * (1.0f / MAXIT);
    }
}

extern "C" void kernel_launch(void* const* d_in, const int* in_sizes, int n_in,
                              void* d_out, int out_size)
{
    const float* lamda = (const float*)d_in[0];
    const float* c_in  = (const float*)d_in[1];
    const float* c_s   = (const float*)d_in[2];
    const float* b_eq  = (const float*)d_in[3];
    const float* Av    = (const float*)d_in[4];
    const float* Aa    = (const float*)d_in[5];
    const float* Ap    = (const float*)d_in[6];
    const float* Qi    = (const float*)d_in[7];
    float* out = (float*)d_out;

    prep_g<<<1, 1024>>>(Av, Aa, Ap);
    prep_m<<<1, 1024>>>(Qi);

    int smem_bytes = SMEM_FLOATS * sizeof(float);
    cudaFuncSetAttribute(proj_filter_kernel,
                         cudaFuncAttributeMaxDynamicSharedMemorySize, smem_bytes);
    proj_filter_kernel<<<BATCH / SPB, NTHREADS, smem_bytes>>>(
        lamda, c_in, c_s, b_eq, Av, Aa, Ap, Qi, out);
}

// round 12
// speedup vs baseline: 1.9784x; 1.0143x over previous
#include <cuda_runtime.h>
#include <math.h>

#define NUMR    100
#define BATCH   2048
#define NVAR    192
#define NEQC    30
#define NHDIM   222
#define MAXIT   15
#define SPB     8
#define NTHREADS 512
#define PIF     3.14159265358979323846f

// shared memory float offsets (54688 floats = 218,752 B)
#define OFF_X    0        // 300*32 = 9600   [u][32]
#define OFF_Y    9600     // 300*48 = 14400  [u][48]
#define OFF_W    24000    // 300*48 = 14400  [u][48]
#define OFF_P    38400    // 48*36 = 1728
#define OFF_QS   40128    // 48*32 = 1536
#define OFF_M11  41664    // 1024 pair layout
#define OFF_MG2  42688    // 1024
#define OFF_DLP  43712    // 3*32*49 = 4704  [t*32+k][49]
#define OFF_PART 48416    // 8*16*49 = 6272  (6,7 = dc buffers)
#define SMEM_FLOATS 54688

typedef unsigned long long ull;

__device__ float M11Pg[1024];
__device__ float MG2Pg[1024];
__device__ float Gpart[8 * 1024];

__device__ __forceinline__ void fma2(ull& d, ull a, ull b) {
    asm("fma.rn.f32x2 %0, %1, %2, %0;" : "+l"(d) : "l"(a), "l"(b));
}
__device__ __forceinline__ float hadd2(ull v) {
    float lo, hi;
    asm("mov.b64 {%0, %1}, %2;" : "=f"(lo), "=f"(hi) : "l"(v));
    return lo + hi;
}
__device__ __forceinline__ float hadd2x2(ull a, ull b) {
    return hadd2(a) + hadd2(b);
}
__device__ __forceinline__ ull pack2(float v) {
    ull r; asm("mov.b64 %0, {%1, %1};" : "=l"(r) : "f"(v)); return r;
}
__device__ __forceinline__ void unpack2(float& lo, float& hi, ull v) {
    asm("mov.b64 {%0, %1}, %2;" : "=f"(lo), "=f"(hi) : "l"(v));
}

// prep1: per-CTA partial outer-product slabs (8 CTAs x 38 rows)
__global__ void prep_g(const float* __restrict__ Av,
                       const float* __restrict__ Aa,
                       const float* __restrict__ Ap)
{
    __shared__ float xs[38 * 32];
    int c = blockIdx.x;
    int tid = threadIdx.x;
    int u0 = c * 38;
    int u1 = (u0 + 38 < 300) ? u0 + 38 : 300;
    int len = u1 - u0;
    for (int idx = tid; idx < len * 32; idx += 1024) {
        int u = u0 + (idx >> 5);
        int col = idx & 31;
        int t = (u >= 100) + (u >= 200);
        const float* A = (t == 0) ? Av : ((t == 1) ? Aa : Ap);
        xs[idx] = A[(u - t * 100) * NVAR + col];
    }
    __syncthreads();
    int a = tid >> 5, b = tid & 31;
    float s0 = 0.f, s1 = 0.f;
#pragma unroll 2
    for (int i = 0; i < len; i += 2) {
        s0 += xs[i * 32 + a] * xs[i * 32 + b];
        if (i + 1 < len)
            s1 += xs[(i + 1) * 32 + a] * xs[(i + 1) * 32 + b];
    }
    Gpart[c * 1024 + tid] = s0 + s1;
}

// prep2: sum partials -> G2 (smem); M11 (pair layout) and M11G2 = M11 @ G2
__global__ void prep_m(const float* __restrict__ Qi)
{
    __shared__ float g2s[1024];
    int tid = threadIdx.x;
    float acc = 0.f;
#pragma unroll
    for (int c = 0; c < 8; c++)
        acc += Gpart[c * 1024 + tid];
    g2s[tid] = 2.f * acc;
    __syncthreads();
    int pos = tid >> 5, k = tid & 31;
    float a0 = 0.f, a1 = 0.f;
#pragma unroll 4
    for (int j = 0; j < 32; j += 2) {
        a0 += Qi[pos * NHDIM + j]     * g2s[j * 32 + k];
        a1 += Qi[pos * NHDIM + j + 1] * g2s[(j + 1) * 32 + k];
    }
    int o = (k >> 1) * 64 + pos * 2 + (k & 1);
    MG2Pg[o] = a0 + a1;
    M11Pg[o] = Qi[pos * NHDIM + k];
}

__global__ void __launch_bounds__(NTHREADS, 1)
proj_filter_kernel(const float* __restrict__ lamda,
                   const float* __restrict__ c_in_g,
                   const float* __restrict__ c_samp,
                   const float* __restrict__ b_eq,
                   const float* __restrict__ Av,
                   const float* __restrict__ Aa,
                   const float* __restrict__ Ap,
                   const float* __restrict__ Qi,
                   float* __restrict__ out)
{
    extern __shared__ float sm[];
    const int tid   = threadIdx.x;
    const int warp  = tid >> 5;
    const int lane  = tid & 31;
    const int samp  = warp >> 1;
    const int h     = warp & 1;
    const int mb    = 3 * h;
    const int s     = blockIdx.x * SPB + samp;
    const int col0  = samp * 6 + mb;
    const int col0s = samp * 6;

    // E role (warp<12): t block, kq 8-k chunk
    const int et = warp >> 2;
    const int kq = warp & 3;

    // ---- stage X and the two 32x32 matrices ----
    for (int idx = tid; idx < 9600; idx += NTHREADS) {
        int t = idx / 3200;
        int rem = idx - t * 3200;
        const float* A = (t == 0) ? Av : ((t == 1) ? Aa : Ap);
        sm[OFF_X + idx] = A[(rem >> 5) * NVAR + (rem & 31)];
    }
    for (int idx = tid; idx < 2048; idx += NTHREADS) {
        if (idx < 1024) sm[OFF_M11 + idx] = M11Pg[idx];
        else            sm[OFF_MG2 + idx - 1024] = MG2Pg[idx - 1024];
    }

    // ---- per-sample state ----
    float cin[3], cprev[3], lsum[3], sdl[3], pbv[3];
#pragma unroll
    for (int m = 0; m < 3; m++) {
        int j = (mb + m) * 32 + lane;
        cin[m]   = c_in_g[s * NVAR + j];
        cprev[m] = c_samp[s * NVAR + j];
        const float* lp = lamda + s * (3 * NVAR) + j;
        lsum[m] = lp[0] + lp[NVAR] + lp[2 * NVAR];
        float a = 0.f;
        const float* bq = b_eq + s * NEQC + (mb + m) * 5;
#pragma unroll
        for (int k = 0; k < 5; k++)
            a += Qi[lane * NHDIM + NVAR + k] * bq[k];
        pbv[m] = a;
    }

#pragma unroll
    for (int m = 0; m < 3; m++)
        sm[OFF_P + (col0 + m) * 36 + lane] = cprev[m];
    __syncthreads();   // X, M11, MG2, P ready

    // ---- D0: y0 and w0 ----
    {
        ull PA[16], PB[16];
        const ulonglong2* PcA = (const ulonglong2*)&sm[OFF_P + lane * 36];
        const ulonglong2* PcB = (const ulonglong2*)&sm[OFF_P + (32 + (lane & 15)) * 36];
#pragma unroll
        for (int q = 0; q < 8; q++) {
            ulonglong2 a = PcA[q]; PA[2*q] = a.x; PA[2*q+1] = a.y;
            ulonglong2 b = PcB[q]; PB[2*q] = b.x; PB[2*q+1] = b.y;
        }
#pragma unroll
        for (int i = 0; i < 19; i++) {
            int u = warp + 16 * i;
            if (u < 300) {
                int t = (u >= 100) + (u >= 200);
                float V = (t == 0) ? 0.8f : ((t == 1) ? 1.8f : PIF);
                const ulonglong2* Xr = (const ulonglong2*)&sm[OFF_X + u * 32];
                ull aA0 = 0, aA1 = 0, aB0 = 0, aB1 = 0;
#pragma unroll
                for (int q = 0; q < 8; q += 2) {
                    ulonglong2 x0 = Xr[q], x1 = Xr[q + 1];
                    fma2(aA0, x0.x, PA[2*q]);   fma2(aA0, x0.y, PA[2*q+1]);
                    fma2(aA1, x1.x, PA[2*q+2]); fma2(aA1, x1.y, PA[2*q+3]);
                    fma2(aB0, x0.x, PB[2*q]);   fma2(aB0, x0.y, PB[2*q+1]);
                    fma2(aB1, x1.x, PB[2*q+2]); fma2(aB1, x1.y, PB[2*q+3]);
                }
                float ynA = hadd2x2(aA0, aA1), ynB = hadd2x2(aB0, aB1);
                sm[OFF_Y + u * 48 + lane] = ynA;
                sm[OFF_W + u * 48 + lane] =
                    fmaxf(ynA - V, 0.f) - fmaxf(-ynA - V, 0.f);
                if (lane < 16) {
                    sm[OFF_Y + u * 48 + 32 + lane] = ynB;
                    sm[OFF_W + u * 48 + 32 + lane] =
                        fmaxf(ynB - V, 0.f) - fmaxf(-ynB - V, 0.f);
                }
            }
        }
    }
    __syncthreads();

    // ---- E0: dl0 partials from W ----
    if (warp < 12) {
        ull dA[4] = {0,0,0,0}, dB[4] = {0,0,0,0};
        for (int u = et * 100; u < et * 100 + 100; u++) {
            const ulonglong2* Xp = (const ulonglong2*)&sm[OFF_X + u * 32 + kq * 8];
            ull wA = pack2(sm[OFF_W + u * 48 + lane]);
            ull wB = pack2(sm[OFF_W + u * 48 + 32 + (lane & 15)]);
            ulonglong2 x0 = Xp[0], x1 = Xp[1];
            fma2(dA[0], x0.x, wA); fma2(dA[1], x0.y, wA);
            fma2(dA[2], x1.x, wA); fma2(dA[3], x1.y, wA);
            fma2(dB[0], x0.x, wB); fma2(dB[1], x0.y, wB);
            fma2(dB[2], x1.x, wB); fma2(dB[3], x1.y, wB);
        }
#pragma unroll
        for (int j = 0; j < 4; j++) {
            float lo, hi;
            int base = OFF_DLP + (et * 32 + kq * 8 + 2 * j) * 49;
            unpack2(lo, hi, dA[j]);
            sm[base + lane] = lo;
            sm[base + 49 + lane] = hi;
            if (lane < 16) {
                unpack2(lo, hi, dB[j]);
                sm[base + 32 + lane] = lo;
                sm[base + 49 + 32 + lane] = hi;
            }
        }
    }
    __syncthreads();

    // ---- sdl0 ----
#pragma unroll
    for (int m = 0; m < 3; m++) sdl[m] = 0.f;
#pragma unroll
    for (int t = 0; t < 3; t++)
#pragma unroll
        for (int m = 0; m < 3; m++)
            sdl[m] += sm[OFF_DLP + (t * 32 + lane) * 49 + col0 + m];

    float fp_sum = 0.f, rp_sum = 0.f;

    for (int it = 0; it < MAXIT; it++) {
        // ======== AB: p_new = M11*(lsum+cin-sdl) + M11G2*p + pb ========
        float dc = 0.f;
        {
#pragma unroll
            for (int m = 0; m < 3; m++)
                sm[OFF_QS + (col0 + m) * 32 + lane] = lsum[m] + cin[m] - sdl[m];
            __syncwarp();
            ull a0m = 0, a0g = 0, a1m = 0, a1g = 0, a2m = 0, a2g = 0;
            const ull* M1 = (const ull*)&sm[OFF_M11];
            const ull* M2 = (const ull*)&sm[OFF_MG2];
            const ull* Q0 = (const ull*)&sm[OFF_QS + (col0    ) * 32];
            const ull* Q1 = (const ull*)&sm[OFF_QS + (col0 + 1) * 32];
            const ull* Q2 = (const ull*)&sm[OFF_QS + (col0 + 2) * 32];
            const ull* P0 = (const ull*)&sm[OFF_P  + (col0    ) * 36];
            const ull* P1 = (const ull*)&sm[OFF_P  + (col0 + 1) * 36];
            const ull* P2 = (const ull*)&sm[OFF_P  + (col0 + 2) * 36];
#pragma unroll 4
            for (int k2 = 0; k2 < 16; k2++) {
                ull mp = M1[k2 * 32 + lane];
                ull gp = M2[k2 * 32 + lane];
                fma2(a0m, mp, Q0[k2]); fma2(a0g, gp, P0[k2]);
                fma2(a1m, mp, Q1[k2]); fma2(a1g, gp, P1[k2]);
                fma2(a2m, mp, Q2[k2]); fma2(a2g, gp, P2[k2]);
            }
            float pn[3];
            pn[0] = hadd2x2(a0m, a0g) + pbv[0];
            pn[1] = hadd2x2(a1m, a1g) + pbv[1];
            pn[2] = hadd2x2(a2m, a2g) + pbv[2];
#pragma unroll
            for (int m = 0; m < 3; m++) {
                float dd = pn[m] - cprev[m];
                dc += dd * dd;
                cprev[m] = pn[m];
                sm[OFF_P + (col0 + m) * 36 + lane] = pn[m];
            }
            sm[OFF_PART + ((6 + (it & 1)) * 16 + warp) * 49 + lane] = dc;
        }
        __syncthreads();   // P_new ready                                  [bar1]

        // ======== D: y/w update + res/ds partials ========
        {
            ull PA[16], PB[16];
            const ulonglong2* PcA = (const ulonglong2*)&sm[OFF_P + lane * 36];
            const ulonglong2* PcB = (const ulonglong2*)&sm[OFF_P + (32 + (lane & 15)) * 36];
#pragma unroll
            for (int q = 0; q < 8; q++) {
                ulonglong2 a = PcA[q]; PA[2*q] = a.x; PA[2*q+1] = a.y;
                ulonglong2 b = PcB[q]; PB[2*q] = b.x; PB[2*q+1] = b.y;
            }
            // ---- A-pass: cols 0-31, rows warp+16i ----
            float ra0A = 0.f, ra1A = 0.f, ra2A = 0.f;
            float da0A = 0.f, da1A = 0.f, da2A = 0.f;
#pragma unroll
            for (int i = 0; i < 19; i++) {
                int u = warp + 16 * i;
                if (u < 300) {
                    int t = (u >= 100) + (u >= 200);
                    float V = (t == 0) ? 0.8f : ((t == 1) ? 1.8f : PIF);
                    const ulonglong2* Xr = (const ulonglong2*)&sm[OFF_X + u * 32];
                    ull aA0 = 0, aA1 = 0;
#pragma unroll
                    for (int q = 0; q < 8; q += 2) {
                        ulonglong2 x0 = Xr[q], x1 = Xr[q + 1];
                        fma2(aA0, x0.x, PA[2*q]);   fma2(aA0, x0.y, PA[2*q+1]);
                        fma2(aA1, x1.x, PA[2*q+2]); fma2(aA1, x1.y, PA[2*q+3]);
                    }
                    float yn = hadd2x2(aA0, aA1);
                    float yo = sm[OFF_Y + u * 48 + lane];
                    float rt = fmaxf(yn - V, 0.f), rb = fmaxf(-yn - V, 0.f);
                    float rr = rt * rt + rb * rb;
                    float d1 = fmaxf(V - yn, 0.f) - fmaxf(V - yo, 0.f);
                    float d2 = fmaxf(V + yn, 0.f) - fmaxf(V + yo, 0.f);
                    float dd = d1 * d1 + d2 * d2;
                    if (t == 0)      { ra0A += rr; da0A += dd; }
                    else if (t == 1) { ra1A += rr; da1A += dd; }
                    else             { ra2A += rr; da2A += dd; }
                    sm[OFF_Y + u * 48 + lane] = yn;
                    sm[OFF_W + u * 48 + lane] = rt - rb;
                }
            }
            // ---- B-pass: cols 32-47, two rows per iter (per-half-warp) ----
            float ra0B = 0.f, ra1B = 0.f, ra2B = 0.f;
            float da0B = 0.f, da1B = 0.f, da2B = 0.f;
            int hoff = (lane >= 16) ? 16 : 0;
#pragma unroll
            for (int j = 0; j < 10; j++) {
                int u = warp + 32 * j + hoff;
                bool valid = (u < 300);
                int uc = valid ? u : 0;
                int t = (uc >= 100) + (uc >= 200);
                float V = (t == 0) ? 0.8f : ((t == 1) ? 1.8f : PIF);
                const ulonglong2* Xr = (const ulonglong2*)&sm[OFF_X + uc * 32];
                ull aB0 = 0, aB1 = 0;
#pragma unroll
                for (int q = 0; q < 8; q += 2) {
                    ulonglong2 x0 = Xr[q], x1 = Xr[q + 1];
                    fma2(aB0, x0.x, PB[2*q]);   fma2(aB0, x0.y, PB[2*q+1]);
                    fma2(aB1, x1.x, PB[2*q+2]); fma2(aB1, x1.y, PB[2*q+3]);
                }
                float yn = hadd2x2(aB0, aB1);
                int yaddr = OFF_Y + uc * 48 + 32 + (lane & 15);
                float yo = sm[yaddr];
                float rt = fmaxf(yn - V, 0.f), rb = fmaxf(-yn - V, 0.f);
                float rr = rt * rt + rb * rb;
                float d1 = fmaxf(V - yn, 0.f) - fmaxf(V - yo, 0.f);
                float d2 = fmaxf(V + yn, 0.f) - fmaxf(V + yo, 0.f);
                float dd = d1 * d1 + d2 * d2;
                if (valid) {
                    if (t == 0)      { ra0B += rr; da0B += dd; }
                    else if (t == 1) { ra1B += rr; da1B += dd; }
                    else             { ra2B += rr; da2B += dd; }
                    sm[yaddr] = yn;
                    sm[OFF_W + uc * 48 + 32 + (lane & 15)] = rt - rb;
                }
            }
            ra0B += __shfl_xor_sync(0xffffffffu, ra0B, 16);
            ra1B += __shfl_xor_sync(0xffffffffu, ra1B, 16);
            ra2B += __shfl_xor_sync(0xffffffffu, ra2B, 16);
            da0B += __shfl_xor_sync(0xffffffffu, da0B, 16);
            da1B += __shfl_xor_sync(0xffffffffu, da1B, 16);
            da2B += __shfl_xor_sync(0xffffffffu, da2B, 16);

            sm[OFF_PART + ((0 * 3 + 0) * 16 + warp) * 49 + lane] = ra0A;
            sm[OFF_PART + ((0 * 3 + 1) * 16 + warp) * 49 + lane] = ra1A;
            sm[OFF_PART + ((0 * 3 + 2) * 16 + warp) * 49 + lane] = ra2A;
            sm[OFF_PART + ((1 * 3 + 0) * 16 + warp) * 49 + lane] = da0A;
            sm[OFF_PART + ((1 * 3 + 1) * 16 + warp) * 49 + lane] = da1A;
            sm[OFF_PART + ((1 * 3 + 2) * 16 + warp) * 49 + lane] = da2A;
            if (lane < 16) {
                sm[OFF_PART + ((0 * 3 + 0) * 16 + warp) * 49 + 32 + lane] = ra0B;
                sm[OFF_PART + ((0 * 3 + 1) * 16 + warp) * 49 + 32 + lane] = ra1B;
                sm[OFF_PART + ((0 * 3 + 2) * 16 + warp) * 49 + 32 + lane] = ra2B;
                sm[OFF_PART + ((1 * 3 + 0) * 16 + warp) * 49 + 32 + lane] = da0B;
                sm[OFF_PART + ((1 * 3 + 1) * 16 + warp) * 49 + 32 + lane] = da1B;
                sm[OFF_PART + ((1 * 3 + 2) * 16 + warp) * 49 + 32 + lane] = da2B;
            }
        }
        __syncthreads();   // Y, W, partials ready                         [bar2]

        // ======== E: dl partials from W (12 warps; t block x 8-k chunk) ========
        if (warp < 12) {
            ull dA[4] = {0,0,0,0}, dB[4] = {0,0,0,0};
            for (int u = et * 100; u < et * 100 + 100; u++) {
                const ulonglong2* Xp = (const ulonglong2*)&sm[OFF_X + u * 32 + kq * 8];
                ull wA = pack2(sm[OFF_W + u * 48 + lane]);
                ull wB = pack2(sm[OFF_W + u * 48 + 32 + (lane & 15)]);
                ulonglong2 x0 = Xp[0], x1 = Xp[1];
                fma2(dA[0], x0.x, wA); fma2(dA[1], x0.y, wA);
                fma2(dA[2], x1.x, wA); fma2(dA[3], x1.y, wA);
                fma2(dB[0], x0.x, wB); fma2(dB[1], x0.y, wB);
                fma2(dB[2], x1.x, wB); fma2(dB[3], x1.y, wB);
            }
#pragma unroll
            for (int j = 0; j < 4; j++) {
                float lo, hi;
                int base = OFF_DLP + (et * 32 + kq * 8 + 2 * j) * 49;
                unpack2(lo, hi, dA[j]);
                sm[base + lane] = lo;
                sm[base + 49 + lane] = hi;
                if (lane < 16) {
                    unpack2(lo, hi, dB[j]);
                    sm[base + 32 + lane] = lo;
                    sm[base + 49 + 32 + lane] = hi;
                }
            }
        }
        __syncthreads();   // DLP ready                                    [bar3]

        // ======== F: lsum/sdl update + full-sample norms ========
        float red[10];
#pragma unroll
        for (int m = 0; m < 3; m++) sdl[m] = 0.f;
#pragma unroll
        for (int t = 0; t < 3; t++) {
            float dls = 0.f;
#pragma unroll
            for (int c = 0; c < 6; c++) {
                float dl = sm[OFF_DLP + (t * 32 + lane) * 49 + col0s + c];
                dls += dl * dl;
                if (c >= mb && c < mb + 3) {
                    lsum[c - mb] -= dl;
                    sdl[c - mb]  += dl;
                }
            }
            red[6 + t] = dls;
        }
#pragma unroll
        for (int q = 0; q < 6; q++) {
            float v = 0.f;
            if (lane < 16) {
                const float* pb_ = &sm[OFF_PART + (q * 16 + lane) * 49 + col0s];
                v = pb_[0] + pb_[1] + pb_[2] + pb_[3] + pb_[4] + pb_[5];
            }
            red[q] = v;
        }
        red[9] = sm[OFF_PART + ((6 + (it & 1)) * 16 + warp) * 49 + lane]
               + sm[OFF_PART + ((6 + (it & 1)) * 16 + (warp ^ 1)) * 49 + lane];

#pragma unroll
        for (int off = 16; off; off >>= 1)
#pragma unroll
            for (int q = 0; q < 10; q++)
                red[q] += __shfl_xor_sync(0xffffffffu, red[q], off);

        rp_sum += sqrtf(red[0]) + sqrtf(red[1]) + sqrtf(red[2]);
        fp_sum += sqrtf(red[3]) + sqrtf(red[4]) + sqrtf(red[5])
                + sqrtf(red[6]) + sqrtf(red[7]) + sqrtf(red[8]) + sqrtf(red[9]);
    }

    // ---- outputs ----
#pragma unroll
    for (int m = 0; m < 3; m++)
        out[s * NVAR + (mb + m) * 32 + lane] = cprev[m];
    if (h == 0 && lane == 0) {
        out[BATCH * NVAR + s]         = fp_sum * (1.0f / MAXIT);
        out[BATCH * NVAR + BATCH + s] = rp_sum * (1.0f / MAXIT);
    }
}

extern "C" void kernel_launch(void* const* d_in, const int* in_sizes, int n_in,
                              void* d_out, int out_size)
{
    const float* lamda = (const float*)d_in[0];
    const float* c_in  = (const float*)d_in[1];
    const float* c_s   = (const float*)d_in[2];
    const float* b_eq  = (const float*)d_in[3];
    const float* Av    = (const float*)d_in[4];
    const float* Aa    = (const float*)d_in[5];
    const float* Ap    = (const float*)d_in[6];
    const float* Qi    = (const float*)d_in[7];
    float* out = (float*)d_out;

    prep_g<<<8, 1024>>>(Av, Aa, Ap);
    prep_m<<<1, 1024>>>(Qi);

    int smem_bytes = SMEM_FLOATS * sizeof(float);
    cudaFuncSetAttribute(proj_filter_kernel,
                         cudaFuncAttributeMaxDynamicSharedMemorySize, smem_bytes);
    proj_filter_kernel<<<BATCH / SPB, NTHREADS, smem_bytes>>>(
        lamda, c_in, c_s, b_eq, Av, Aa, Ap, Qi, out);
}